// round 4
// baseline (speedup 1.0000x reference)
#include <cuda_runtime.h>
#include <math.h>
#include <stdint.h>

// Problem constants
#define Mm 4
#define Pp 4
#define Ll 2
#define Ss 256
#define Bb 32
#define Ii 256
#define Hh 512
#define Oo 256
#define Gg (3*Hh)     // 1536
#define Rr (Pp*Bb)    // 128 rows per model in the recurrence

#define WROW 516                 // padded smem row stride (floats) for weights
#define SMEM_FLOATS (2*48*WROW + 8*16*36)
#define SMEM_BYTES  (SMEM_FLOATS*4)

// ---------------- scratch (device globals; no allocation) ----------------
__device__ float g_gi0[(size_t)Mm*Ss*Bb*Gg];
__device__ float g_y0m[(size_t)Mm*Pp*Ss*Bb*Hh];
__device__ float g_gi1[(size_t)Mm*Pp*Ss*Bb*Gg];
__device__ float g_a1 [(size_t)Mm*Pp*Ss*Bb*Hh];
__device__ float g_h0a[Mm*Rr*Hh];
__device__ float g_h0b[Mm*Rr*Hh];
__device__ float g_h1a[Mm*Rr*Hh];
__device__ float g_h1b[Mm*Rr*Hh];
__device__ float g_whh_hi[2 * Mm * Gg * Hh];
__device__ float g_whh_lo[2 * Mm * Gg * Hh];
__device__ unsigned g_sync[8];   // per (layer, model) barrier counters

// ---------------- helpers ----------------
__device__ __forceinline__ float tf32r(float x) {
    uint32_t u;
    asm("cvt.rna.tf32.f32 %0, %1;" : "=r"(u) : "f"(x));
    return __uint_as_float(u);
}

__device__ __forceinline__ void mma_tf32(float c[4], const uint32_t a[4], const uint32_t b[2]) {
    asm volatile(
        "mma.sync.aligned.m16n8k8.row.col.f32.tf32.tf32.f32 "
        "{%0,%1,%2,%3},{%4,%5,%6,%7},{%8,%9},{%0,%1,%2,%3};"
        : "+f"(c[0]), "+f"(c[1]), "+f"(c[2]), "+f"(c[3])
        : "r"(a[0]), "r"(a[1]), "r"(a[2]), "r"(a[3]), "r"(b[0]), "r"(b[1]));
}

__device__ __forceinline__ float sigmoidf_(float x) { return 1.0f / (1.0f + expf(-x)); }

// permuted position within a k8-group: (k+tig, k+4+tig) become an adjacent pair
__device__ __forceinline__ int kperm(int k) {
    int k8 = k >> 3, r = k & 7;
    return k8 * 8 + ((r < 4) ? 2 * r : 2 * (r - 4) + 1);
}

// ---------------- init hidden + zero sync counters ----------------
__global__ void init_hidden_kernel(const float* __restrict__ hidden,
                                   float* __restrict__ h0, float* __restrict__ h1,
                                   unsigned* __restrict__ sync)
{
    int idx = blockIdx.x * blockDim.x + threadIdx.x;
    if (blockIdx.x == 0 && threadIdx.x < 8) sync[threadIdx.x] = 0u;
    const int n = Mm*Pp*Bb*Hh;
    if (idx >= n) return;
    int mp  = idx / (Bb*Hh);
    int rem = idx % (Bb*Hh);
    h0[idx] = hidden[((size_t)mp*Ll + 0)*Bb*Hh + rem];
    h1[idx] = hidden[((size_t)mp*Ll + 1)*Bb*Hh + rem];
}

__global__ void hidden_out_kernel(const float* __restrict__ h0, const float* __restrict__ h1,
                                  float* __restrict__ out)
{
    int idx = blockIdx.x * blockDim.x + threadIdx.x;
    const int n = Mm*Pp*Bb*Hh;
    if (idx >= n) return;
    int mp  = idx / (Bb*Hh);
    int rem = idx % (Bb*Hh);
    out[((size_t)mp*Ll + 0)*Bb*Hh + rem] = h0[idx];
    out[((size_t)mp*Ll + 1)*Bb*Hh + rem] = h1[idx];
}

// ---------------- split weights into tf32 hi/lo ----------------
__global__ void split_hilo_kernel(const float* __restrict__ w0, const float* __restrict__ w1,
                                  float* __restrict__ hi, float* __restrict__ lo)
{
    const int n = Mm * Gg * Hh;
    int idx = blockIdx.x * blockDim.x + threadIdx.x;
    if (idx >= 2 * n) return;
    float x = (idx < n) ? w0[idx] : w1[idx - n];
    float h = tf32r(x);
    hi[idx] = h;
    lo[idx] = tf32r(x - h);
}

// ================= TF32 tensor-core GEMM with bias (feedforward) =================
__global__ __launch_bounds__(256) void gemm_tf32_bias(
    const float* __restrict__ A, long aStride,
    const float* __restrict__ W, long wStride,
    const float* __restrict__ bias, int bStride,
    float* __restrict__ C, long cStride,
    int rows, int N, int K)
{
    const int batch = blockIdx.z;
    A    += (long)batch * aStride;
    W    += (long)batch * wStride;
    bias += (long)batch * bStride;
    C    += (long)batch * cStride;

    const int r0 = blockIdx.y * 128;
    const int n0 = blockIdx.x * 64;

    __shared__ float As[128][36];
    __shared__ float Bs[64][36];

    const int tid  = threadIdx.x;
    const int lane = tid & 31;
    const int w    = tid >> 5;
    const int wr   = w >> 1;
    const int wc   = w & 1;
    const int gID  = lane >> 2;
    const int tig  = lane & 3;

    float c[2][4][4];
#pragma unroll
    for (int mi = 0; mi < 2; mi++)
#pragma unroll
        for (int ni = 0; ni < 4; ni++)
#pragma unroll
            for (int q = 0; q < 4; q++) c[mi][ni][q] = 0.f;

    for (int k0 = 0; k0 < K; k0 += 32) {
#pragma unroll
        for (int l = 0; l < 4; l++) {
            int f = tid + l * 256;
            int row = f >> 3;
            int kg  = f & 7;
            float4 v = *reinterpret_cast<const float4*>(&A[(long)(r0 + row) * K + k0 + kg * 4]);
            float4 t;
            t.x = tf32r(v.x); t.y = tf32r(v.y); t.z = tf32r(v.z); t.w = tf32r(v.w);
            *reinterpret_cast<float4*>(&As[row][kg * 4]) = t;
        }
#pragma unroll
        for (int l = 0; l < 2; l++) {
            int f = tid + l * 256;
            int col = f >> 3;
            int kg  = f & 7;
            float4 v = *reinterpret_cast<const float4*>(&W[(long)(n0 + col) * K + k0 + kg * 4]);
            float4 t;
            t.x = tf32r(v.x); t.y = tf32r(v.y); t.z = tf32r(v.z); t.w = tf32r(v.w);
            *reinterpret_cast<float4*>(&Bs[col][kg * 4]) = t;
        }
        __syncthreads();

#pragma unroll
        for (int k8 = 0; k8 < 4; k8++) {
            const int kb = k8 * 8;
            uint32_t af[2][4];
#pragma unroll
            for (int mi = 0; mi < 2; mi++) {
                int rb = wr * 32 + mi * 16 + gID;
                af[mi][0] = __float_as_uint(As[rb    ][kb + tig]);
                af[mi][1] = __float_as_uint(As[rb + 8][kb + tig]);
                af[mi][2] = __float_as_uint(As[rb    ][kb + 4 + tig]);
                af[mi][3] = __float_as_uint(As[rb + 8][kb + 4 + tig]);
            }
            uint32_t bf[4][2];
#pragma unroll
            for (int ni = 0; ni < 4; ni++) {
                int cb = wc * 32 + ni * 8 + gID;
                bf[ni][0] = __float_as_uint(Bs[cb][kb + tig]);
                bf[ni][1] = __float_as_uint(Bs[cb][kb + 4 + tig]);
            }
#pragma unroll
            for (int mi = 0; mi < 2; mi++)
#pragma unroll
                for (int ni = 0; ni < 4; ni++)
                    mma_tf32(c[mi][ni], af[mi], bf[ni]);
        }
        __syncthreads();
    }

#pragma unroll
    for (int mi = 0; mi < 2; mi++) {
#pragma unroll
        for (int ni = 0; ni < 4; ni++) {
            int row = r0 + wr * 32 + mi * 16 + gID;
            int col = n0 + wc * 32 + ni * 8 + 2 * tig;
            float b0 = bias[col], b1 = bias[col + 1];
            float2 v0 = make_float2(c[mi][ni][0] + b0, c[mi][ni][1] + b1);
            float2 v1 = make_float2(c[mi][ni][2] + b0, c[mi][ni][3] + b1);
            *reinterpret_cast<float2*>(&C[(long)row * N + col]) = v0;
            *reinterpret_cast<float2*>(&C[(long)(row + 8) * N + col]) = v1;
        }
    }
}

// ================= persistent GRU scan: weights resident in SMEM =================
// grid = 128 blocks (1/SM): m = bx>>5, j0 = (bx&31)*16. 256 threads = 8 warps.
// Each warp owns a 16-row stripe; block covers all 128 rows x 16 j-cols x 3 gates.
// Per-model spin barrier between timesteps (32 blocks per model, all co-resident).
template<int LAYER>
__global__ __launch_bounds__(256, 1) void gru_scan(
    float* __restrict__ bufA, float* __restrict__ bufB,
    const float* __restrict__ gi,
    const float* __restrict__ whh_hi, const float* __restrict__ whh_lo,
    const float* __restrict__ bhh,
    const float* __restrict__ dm,
    float* __restrict__ outact,
    unsigned* __restrict__ syncctr)
{
    extern __shared__ float smf[];
    float* Wh = smf;
    float* Wl = smf + 48 * WROW;
    float* As = smf + 2 * 48 * WROW;   // [8 warps][16 rows][36]

    const int bx = blockIdx.x;
    const int m  = bx >> 5;
    const int j0 = (bx & 31) * 16;

    const int tid  = threadIdx.x;
    const int lane = tid & 31;
    const int w    = tid >> 5;
    const int gID  = lane >> 2;
    const int tig  = lane & 3;

    const float* Whb = whh_hi + (long)m * Gg * Hh;
    const float* Wlb = whh_lo + (long)m * Gg * Hh;

    // ---- load weights into smem once, fragment-permuted ----
    for (int f = tid; f < 2 * 48 * 128; f += 256) {
        int sel = (f >= 48 * 128);
        int idx = sel ? f - 48 * 128 : f;
        int cc = idx >> 7;            // 0..47
        int q  = idx & 127;
        int kk = q * 4;
        int gate = cc >> 4, jloc = cc & 15;
        const float* src = (sel ? Wlb : Whb) + (long)(gate * Hh + j0 + jloc) * Hh + kk;
        float4 v = *reinterpret_cast<const float4*>(src);
        float* dstrow = (sel ? Wl : Wh) + cc * WROW;
        float vv[4] = {v.x, v.y, v.z, v.w};
#pragma unroll
        for (int e = 0; e < 4; e++)
            dstrow[kperm(kk + e)] = vv[e];
    }
    __syncthreads();

    float* Aw = As + w * (16 * 36);
    const long hbase = (long)m * Rr * Hh;
    const int  rwarp = w * 16;

    // ---- prefetch biases (constant across steps) ----
    float b_r[2][2], b_z[2][2], b_n[2][2];
#pragma unroll
    for (int u = 0; u < 2; u++)
#pragma unroll
        for (int jj = 0; jj < 2; jj++) {
            int j = j0 + u * 8 + 2 * tig + jj;
            b_r[u][jj] = __ldg(&bhh[m * Gg + j]);
            b_z[u][jj] = __ldg(&bhh[m * Gg + Hh + j]);
            b_n[u][jj] = __ldg(&bhh[m * Gg + 2 * Hh + j]);
        }

    for (int t = 0; t < Ss; t++) {
        const float* hc = (t & 1) ? bufB : bufA;
        float*       hn = (t & 1) ? bufA : bufB;

        // ---- prefetch gi + hold for this step ----
        float gir[2][2][2], giz[2][2][2], gin[2][2][2], hold[2][2][2];
#pragma unroll
        for (int rh = 0; rh < 2; rh++) {
            int r = rwarp + gID + rh * 8;
            int p = r >> 5, b = r & 31;
            long girow = (LAYER == 0)
                ? ((long)(m * Ss + t) * Bb + b) * Gg
                : ((long)((m * Pp + p) * Ss + t) * Bb + b) * Gg;
#pragma unroll
            for (int u = 0; u < 2; u++)
#pragma unroll
                for (int jj = 0; jj < 2; jj++) {
                    int j = j0 + u * 8 + 2 * tig + jj;
                    gir[rh][u][jj] = __ldg(&gi[girow + j]);
                    giz[rh][u][jj] = __ldg(&gi[girow + Hh + j]);
                    gin[rh][u][jj] = __ldg(&gi[girow + 2 * Hh + j]);
                    hold[rh][u][jj] = __ldcg(&hc[hbase + (long)r * Hh + j]);
                }
        }

        float c[6][4];
#pragma unroll
        for (int tI = 0; tI < 6; tI++)
#pragma unroll
            for (int q = 0; q < 4; q++) c[tI][q] = 0.f;

        for (int kt = 0; kt < 16; kt++) {
            // stage this warp's 16 rows x 32 k chunk (permuted)
#pragma unroll
            for (int qq = 0; qq < 4; qq++) {
                int f = lane + qq * 32;
                int row = f >> 3, kg = f & 7;
                float4 v = __ldcg(reinterpret_cast<const float4*>(
                    &hc[hbase + (long)(rwarp + row) * Hh + kt * 32 + kg * 4]));
                float vv[4] = {v.x, v.y, v.z, v.w};
#pragma unroll
                for (int e = 0; e < 4; e++)
                    Aw[row * 36 + kperm(kg * 4 + e)] = vv[e];
            }
            __syncwarp();

#pragma unroll
            for (int k8 = 0; k8 < 4; k8++) {
                float2 pa0 = *reinterpret_cast<const float2*>(&Aw[gID * 36 + k8 * 8 + tig * 2]);
                float2 pa1 = *reinterpret_cast<const float2*>(&Aw[(gID + 8) * 36 + k8 * 8 + tig * 2]);
                float x0 = pa0.x, x2 = pa0.y, x1 = pa1.x, x3 = pa1.y;
                float h0 = tf32r(x0), h1 = tf32r(x1), h2 = tf32r(x2), h3 = tf32r(x3);
                uint32_t ahi[4] = {__float_as_uint(h0), __float_as_uint(h1),
                                   __float_as_uint(h2), __float_as_uint(h3)};
                uint32_t alo[4] = {__float_as_uint(tf32r(x0 - h0)), __float_as_uint(tf32r(x1 - h1)),
                                   __float_as_uint(tf32r(x2 - h2)), __float_as_uint(tf32r(x3 - h3))};
                const int kpos = kt * 32 + k8 * 8 + tig * 2;
#pragma unroll
                for (int tI = 0; tI < 6; tI++) {
                    int cc = tI * 8 + gID;
                    float2 bh2 = *reinterpret_cast<const float2*>(&Wh[cc * WROW + kpos]);
                    float2 bl2 = *reinterpret_cast<const float2*>(&Wl[cc * WROW + kpos]);
                    uint32_t bh[2] = {__float_as_uint(bh2.x), __float_as_uint(bh2.y)};
                    uint32_t bl[2] = {__float_as_uint(bl2.x), __float_as_uint(bl2.y)};
                    mma_tf32(c[tI], ahi, bh);
                    mma_tf32(c[tI], ahi, bl);
                    mma_tf32(c[tI], alo, bh);
                }
            }
            __syncwarp();
        }

        // ---- epilogue: gates + h update ----
#pragma unroll
        for (int rh = 0; rh < 2; rh++) {
            int r = rwarp + gID + rh * 8;
            int p = r >> 5, b = r & 31;
            long obase = (((long)(m * Pp + p) * Ss + t) * Bb + b) * Hh;
#pragma unroll
            for (int u = 0; u < 2; u++)
#pragma unroll
                for (int jj = 0; jj < 2; jj++) {
                    int j = j0 + u * 8 + 2 * tig + jj;
                    int q = rh * 2 + jj;
                    float ghr = c[0 + u][q] + b_r[u][jj];
                    float ghz = c[2 + u][q] + b_z[u][jj];
                    float ghn = c[4 + u][q] + b_n[u][jj];
                    float rg = sigmoidf_(gir[rh][u][jj] + ghr);
                    float zg = sigmoidf_(giz[rh][u][jj] + ghz);
                    float ng = tanhf(gin[rh][u][jj] + rg * ghn);
                    float hnew = (1.0f - zg) * ng + zg * hold[rh][u][jj];
                    __stcg(&hn[hbase + (long)r * Hh + j], hnew);
                    long oidx = obase + j;
                    if (LAYER == 0)
                        outact[oidx] = hnew * __ldg(&dm[oidx]);
                    else
                        outact[oidx] = fmaxf(hnew, 0.f) + 0.01f * fminf(hnew, 0.f);
                }
        }

        // ---- per-model grid barrier ----
        __syncthreads();
        if (tid == 0) {
            __threadfence();
            atomicAdd(&syncctr[m], 1u);
            unsigned target = 32u * (unsigned)(t + 1);
            volatile unsigned* vc = (volatile unsigned*)&syncctr[m];
            while (*vc < target) __nanosleep(64);
        }
        __syncthreads();
    }
}

// ---------------- mean / var ----------------
__global__ void meanvar_kernel(const float* __restrict__ preds,
                               float* __restrict__ out_mean, float* __restrict__ out_var)
{
    const int n = Ss * Bb * Oo;
    int idx = blockIdx.x * blockDim.x + threadIdx.x;
    if (idx >= n) return;
    float v[16];
    float s = 0.f;
#pragma unroll
    for (int mp = 0; mp < 16; mp++) {
        v[mp] = preds[(long)mp * n + idx];
        s += v[mp];
    }
    float mu = s * (1.0f / 16.0f);
    float q = 0.f;
#pragma unroll
    for (int mp = 0; mp < 16; mp++) {
        float d = v[mp] - mu;
        q += d * d;
    }
    out_mean[idx] = mu;
    out_var[idx]  = q * (1.0f / 15.0f);
}

// ---------------- host launch ----------------
extern "C" void kernel_launch(void* const* d_in, const int* in_sizes, int n_in,
                              void* d_out, int out_size)
{
    const float* input  = (const float*)d_in[0];
    const float* hidden = (const float*)d_in[1];
    const float* w_ih0  = (const float*)d_in[2];
    const float* w_hh0  = (const float*)d_in[3];
    const float* b_ih0  = (const float*)d_in[4];
    const float* b_hh0  = (const float*)d_in[5];
    const float* w_ih1  = (const float*)d_in[6];
    const float* w_hh1  = (const float*)d_in[7];
    const float* b_ih1  = (const float*)d_in[8];
    const float* b_hh1  = (const float*)d_in[9];
    const float* lin_w  = (const float*)d_in[10];
    const float* lin_b  = (const float*)d_in[11];
    const float* dm     = (const float*)d_in[12];

    float* out = (float*)d_out;
    float* out_mean   = out;
    float* out_var    = out + (size_t)Ss * Bb * Oo;
    float* preds      = out + 2 * (size_t)Ss * Bb * Oo;
    float* hidden_out = preds + (size_t)Mm * Pp * Ss * Bb * Oo;

    float *gi0, *y0m, *gi1, *a1, *h0a, *h0b, *h1a, *h1b, *whh_hi, *whh_lo;
    unsigned* syncp;
    cudaGetSymbolAddress((void**)&gi0, g_gi0);
    cudaGetSymbolAddress((void**)&y0m, g_y0m);
    cudaGetSymbolAddress((void**)&gi1, g_gi1);
    cudaGetSymbolAddress((void**)&a1,  g_a1);
    cudaGetSymbolAddress((void**)&h0a, g_h0a);
    cudaGetSymbolAddress((void**)&h0b, g_h0b);
    cudaGetSymbolAddress((void**)&h1a, g_h1a);
    cudaGetSymbolAddress((void**)&h1b, g_h1b);
    cudaGetSymbolAddress((void**)&whh_hi, g_whh_hi);
    cudaGetSymbolAddress((void**)&whh_lo, g_whh_lo);
    cudaGetSymbolAddress((void**)&syncp, g_sync);

    const int WN = Mm * Gg * Hh;

    cudaFuncSetAttribute(gru_scan<0>, cudaFuncAttributeMaxDynamicSharedMemorySize, SMEM_BYTES);
    cudaFuncSetAttribute(gru_scan<1>, cudaFuncAttributeMaxDynamicSharedMemorySize, SMEM_BYTES);

    // 0) split recurrent weights into hi/lo
    split_hilo_kernel<<<(2 * WN + 255) / 256, 256>>>(w_hh0, w_hh1, whh_hi, whh_lo);

    // 1) init hidden + zero barrier counters
    init_hidden_kernel<<<(Mm*Pp*Bb*Hh + 255) / 256, 256>>>(hidden, h0a, h1a, syncp);

    // 2) gi0 = input @ w_ih0^T + b_ih0  (TF32)
    {
        dim3 grid(Gg / 64, (Ss * Bb) / 128, Mm);
        gemm_tf32_bias<<<grid, 256>>>(input, 0L,
                                      w_ih0, (long)Gg * Ii,
                                      b_ih0, Gg,
                                      gi0, (long)Ss * Bb * Gg,
                                      Ss * Bb, Gg, Ii);
    }

    // 3) layer-0 persistent scan
    gru_scan<0><<<128, 256, SMEM_BYTES>>>(h0a, h0b, gi0, whh_hi, whh_lo,
                                          b_hh0, dm, y0m, syncp);

    // 4) gi1 = y0m @ w_ih1^T + b_ih1 (TF32)
    {
        dim3 grid(Gg / 64, (Pp * Ss * Bb) / 128, Mm);
        gemm_tf32_bias<<<grid, 256>>>(y0m, (long)Pp * Ss * Bb * Hh,
                                      w_ih1, (long)Gg * Hh,
                                      b_ih1, Gg,
                                      gi1, (long)Pp * Ss * Bb * Gg,
                                      Pp * Ss * Bb, Gg, Hh);
    }

    // 5) layer-1 persistent scan (separate counters)
    gru_scan<1><<<128, 256, SMEM_BYTES>>>(h1a, h1b, gi1, whh_hi + WN, whh_lo + WN,
                                          b_hh1, nullptr, a1, syncp + 4);

    // 6) preds = a1 @ lin_w^T + lin_b (TF32)
    {
        dim3 grid(Oo / 64, (Pp * Ss * Bb) / 128, Mm);
        gemm_tf32_bias<<<grid, 256>>>(a1, (long)Pp * Ss * Bb * Hh,
                                      lin_w, (long)Oo * Hh,
                                      lin_b, Oo,
                                      preds, (long)Pp * Ss * Bb * Oo,
                                      Pp * Ss * Bb, Oo, Hh);
    }

    // 7) mean / var
    meanvar_kernel<<<(Ss * Bb * Oo + 255) / 256, 256>>>(preds, out_mean, out_var);

    // 8) hidden out (256 steps even -> final h back in 'a' buffers)
    hidden_out_kernel<<<(Mm*Pp*Bb*Hh + 255) / 256, 256>>>(h0a, h1a, hidden_out);
}

// round 5
// speedup vs baseline: 1.2362x; 1.2362x over previous
#include <cuda_runtime.h>
#include <cuda_bf16.h>
#include <math.h>
#include <stdint.h>

// Problem constants
#define Mm 4
#define Pp 4
#define Ll 2
#define Ss 256
#define Bb 32
#define Ii 256
#define Hh 512
#define Oo 256
#define Gg (3*Hh)     // 1536
#define Rr (Pp*Bb)    // 128 rows per model in the recurrence

#define STW 524       // smem weight row stride in 32-bit words (per gate-col)
#define SCAN_SMEM_BYTES (48*STW*4 + 12*32*48*4)   // 100608 + 73728 = 174336

// ---------------- scratch (device globals; no allocation) ----------------
__device__ float g_gi0[(size_t)Mm*Ss*Bb*Gg];
__device__ float g_y0m[(size_t)Mm*Pp*Ss*Bb*Hh];
__device__ float g_gi1[(size_t)Mm*Pp*Ss*Bb*Gg];
__device__ float g_a1 [(size_t)Mm*Pp*Ss*Bb*Hh];
__device__ float g_h0a[Mm*Rr*Hh];
__device__ float g_h0b[Mm*Rr*Hh];
__device__ float g_h1a[Mm*Rr*Hh];
__device__ float g_h1b[Mm*Rr*Hh];
// packed bf16 (hi,lo) versions of h, double buffered, per layer
__device__ uint2 g_hp0a[Mm*Rr*(Hh/2)];
__device__ uint2 g_hp0b[Mm*Rr*(Hh/2)];
__device__ uint2 g_hp1a[Mm*Rr*(Hh/2)];
__device__ uint2 g_hp1b[Mm*Rr*(Hh/2)];
// packed bf16 (hi,lo) recurrent weights: [layer][M][3H][Hh/2] as uint2 (uint4-aligned)
__device__ uint4 g_whhp[2 * Mm * Gg * 128];
__device__ unsigned g_sync[8];

// ---------------- helpers ----------------
__device__ __forceinline__ float tf32r(float x) {
    uint32_t u;
    asm("cvt.rna.tf32.f32 %0, %1;" : "=r"(u) : "f"(x));
    return __uint_as_float(u);
}

__device__ __forceinline__ void mma_tf32(float c[4], const uint32_t a[4], const uint32_t b[2]) {
    asm volatile(
        "mma.sync.aligned.m16n8k8.row.col.f32.tf32.tf32.f32 "
        "{%0,%1,%2,%3},{%4,%5,%6,%7},{%8,%9},{%0,%1,%2,%3};"
        : "+f"(c[0]), "+f"(c[1]), "+f"(c[2]), "+f"(c[3])
        : "r"(a[0]), "r"(a[1]), "r"(a[2]), "r"(a[3]), "r"(b[0]), "r"(b[1]));
}

__device__ __forceinline__ void mma_bf16(float c[4], const uint32_t a[4], const uint32_t b[2]) {
    asm volatile(
        "mma.sync.aligned.m16n8k16.row.col.f32.bf16.bf16.f32 "
        "{%0,%1,%2,%3},{%4,%5,%6,%7},{%8,%9},{%0,%1,%2,%3};"
        : "+f"(c[0]), "+f"(c[1]), "+f"(c[2]), "+f"(c[3])
        : "r"(a[0]), "r"(a[1]), "r"(a[2]), "r"(a[3]), "r"(b[0]), "r"(b[1]));
}

__device__ __forceinline__ float sigmoidf_(float x) { return 1.0f / (1.0f + expf(-x)); }

// pack two fp32 into (bf16-hi word, bf16-lo word)
__device__ __forceinline__ uint2 pack_hilo(float x0, float x1) {
    __nv_bfloat162 hi = __floats2bfloat162_rn(x0, x1);
    float l0 = x0 - __bfloat162float(hi.x);
    float l1 = x1 - __bfloat162float(hi.y);
    __nv_bfloat162 lo = __floats2bfloat162_rn(l0, l1);
    uint2 r;
    r.x = *reinterpret_cast<unsigned*>(&hi);
    r.y = *reinterpret_cast<unsigned*>(&lo);
    return r;
}

// ---------------- init hidden (fp32 + packed) + zero sync ----------------
__global__ void init_hidden_kernel(const float* __restrict__ hidden,
                                   float* __restrict__ h0, float* __restrict__ h1,
                                   uint2* __restrict__ p0, uint2* __restrict__ p1,
                                   unsigned* __restrict__ sync)
{
    int idx = blockIdx.x * blockDim.x + threadIdx.x;
    if (blockIdx.x == 0 && threadIdx.x < 8) sync[threadIdx.x] = 0u;
    const int n2 = Mm*Pp*Bb*(Hh/2);
    if (idx >= n2) return;
    int mp  = idx / (Bb*(Hh/2));
    int rem = idx % (Bb*(Hh/2));
    float2 v0 = *reinterpret_cast<const float2*>(&hidden[((size_t)mp*Ll + 0)*Bb*Hh + rem*2]);
    float2 v1 = *reinterpret_cast<const float2*>(&hidden[((size_t)mp*Ll + 1)*Bb*Hh + rem*2]);
    *reinterpret_cast<float2*>(&h0[(size_t)mp*Bb*Hh + rem*2]) = v0;
    *reinterpret_cast<float2*>(&h1[(size_t)mp*Bb*Hh + rem*2]) = v1;
    p0[(size_t)mp*Bb*(Hh/2) + rem] = pack_hilo(v0.x, v0.y);
    p1[(size_t)mp*Bb*(Hh/2) + rem] = pack_hilo(v1.x, v1.y);
}

__global__ void hidden_out_kernel(const float* __restrict__ h0, const float* __restrict__ h1,
                                  float* __restrict__ out)
{
    int idx = blockIdx.x * blockDim.x + threadIdx.x;
    const int n = Mm*Pp*Bb*Hh;
    if (idx >= n) return;
    int mp  = idx / (Bb*Hh);
    int rem = idx % (Bb*Hh);
    out[((size_t)mp*Ll + 0)*Bb*Hh + rem] = h0[idx];
    out[((size_t)mp*Ll + 1)*Bb*Hh + rem] = h1[idx];
}

// ---------------- split weights into packed bf16 hi/lo words ----------------
__global__ void split_pack_kernel(const float* __restrict__ w0, const float* __restrict__ w1,
                                  uint2* __restrict__ outp)
{
    const int n = Mm * Gg * (Hh/2);
    int idx = blockIdx.x * blockDim.x + threadIdx.x;
    if (idx >= 2 * n) return;
    const float* src = (idx < n) ? w0 : w1;
    int within = (idx < n) ? idx : idx - n;
    float2 x = *reinterpret_cast<const float2*>(src + (size_t)within * 2);
    outp[idx] = pack_hilo(x.x, x.y);
}

// ================= TF32 tensor-core GEMM with bias (feedforward) =================
__global__ __launch_bounds__(256) void gemm_tf32_bias(
    const float* __restrict__ A, long aStride,
    const float* __restrict__ W, long wStride,
    const float* __restrict__ bias, int bStride,
    float* __restrict__ C, long cStride,
    int rows, int N, int K)
{
    const int batch = blockIdx.z;
    A    += (long)batch * aStride;
    W    += (long)batch * wStride;
    bias += (long)batch * bStride;
    C    += (long)batch * cStride;

    const int r0 = blockIdx.y * 128;
    const int n0 = blockIdx.x * 64;

    __shared__ float As[128][36];
    __shared__ float Bs[64][36];

    const int tid  = threadIdx.x;
    const int lane = tid & 31;
    const int w    = tid >> 5;
    const int wr   = w >> 1;
    const int wc   = w & 1;
    const int gID  = lane >> 2;
    const int tig  = lane & 3;

    float c[2][4][4];
#pragma unroll
    for (int mi = 0; mi < 2; mi++)
#pragma unroll
        for (int ni = 0; ni < 4; ni++)
#pragma unroll
            for (int q = 0; q < 4; q++) c[mi][ni][q] = 0.f;

    for (int k0 = 0; k0 < K; k0 += 32) {
#pragma unroll
        for (int l = 0; l < 4; l++) {
            int f = tid + l * 256;
            int row = f >> 3;
            int kg  = f & 7;
            float4 v = *reinterpret_cast<const float4*>(&A[(long)(r0 + row) * K + k0 + kg * 4]);
            float4 t;
            t.x = tf32r(v.x); t.y = tf32r(v.y); t.z = tf32r(v.z); t.w = tf32r(v.w);
            *reinterpret_cast<float4*>(&As[row][kg * 4]) = t;
        }
#pragma unroll
        for (int l = 0; l < 2; l++) {
            int f = tid + l * 256;
            int col = f >> 3;
            int kg  = f & 7;
            float4 v = *reinterpret_cast<const float4*>(&W[(long)(n0 + col) * K + k0 + kg * 4]);
            float4 t;
            t.x = tf32r(v.x); t.y = tf32r(v.y); t.z = tf32r(v.z); t.w = tf32r(v.w);
            *reinterpret_cast<float4*>(&Bs[col][kg * 4]) = t;
        }
        __syncthreads();

#pragma unroll
        for (int k8 = 0; k8 < 4; k8++) {
            const int kb = k8 * 8;
            uint32_t af[2][4];
#pragma unroll
            for (int mi = 0; mi < 2; mi++) {
                int rb = wr * 32 + mi * 16 + gID;
                af[mi][0] = __float_as_uint(As[rb    ][kb + tig]);
                af[mi][1] = __float_as_uint(As[rb + 8][kb + tig]);
                af[mi][2] = __float_as_uint(As[rb    ][kb + 4 + tig]);
                af[mi][3] = __float_as_uint(As[rb + 8][kb + 4 + tig]);
            }
            uint32_t bf[4][2];
#pragma unroll
            for (int ni = 0; ni < 4; ni++) {
                int cb = wc * 32 + ni * 8 + gID;
                bf[ni][0] = __float_as_uint(Bs[cb][kb + tig]);
                bf[ni][1] = __float_as_uint(Bs[cb][kb + 4 + tig]);
            }
#pragma unroll
            for (int mi = 0; mi < 2; mi++)
#pragma unroll
                for (int ni = 0; ni < 4; ni++)
                    mma_tf32(c[mi][ni], af[mi], bf[ni]);
        }
        __syncthreads();
    }

#pragma unroll
    for (int mi = 0; mi < 2; mi++) {
#pragma unroll
        for (int ni = 0; ni < 4; ni++) {
            int row = r0 + wr * 32 + mi * 16 + gID;
            int col = n0 + wc * 32 + ni * 8 + 2 * tig;
            float b0 = bias[col], b1 = bias[col + 1];
            float2 v0 = make_float2(c[mi][ni][0] + b0, c[mi][ni][1] + b1);
            float2 v1 = make_float2(c[mi][ni][2] + b0, c[mi][ni][3] + b1);
            *reinterpret_cast<float2*>(&C[(long)row * N + col]) = v0;
            *reinterpret_cast<float2*>(&C[(long)(row + 8) * N + col]) = v1;
        }
    }
}

// ================= persistent GRU scan: bf16-3 mma, direct-LDG A frags =================
// grid = 128 blocks (m = bx>>5, j0 = (bx&31)*16), 512 threads = 16 warps.
// warp w: row-group r = w&3 (32 rows, 2 m16 tiles), K-quarter q = w>>2 (128 k).
// Partial sums reduced across q via smem; q==0 warps run the epilogue.
template<int LAYER>
__global__ __launch_bounds__(512, 1) void gru_scan(
    float* __restrict__ bufA, float* __restrict__ bufB,
    uint2* __restrict__ pakA, uint2* __restrict__ pakB,
    const float* __restrict__ gi,
    const uint4* __restrict__ whp,   // layer base already applied
    const float* __restrict__ bhh,
    const float* __restrict__ dm,
    float* __restrict__ outact,
    unsigned* __restrict__ syncctr)
{
    extern __shared__ unsigned smw[];
    unsigned* Wpk = smw;                          // 48 x STW words
    float* part = (float*)(smw + 48 * STW);       // 12 x 32 x 48 floats

    const int bx = blockIdx.x;
    const int m  = bx >> 5;
    const int j0 = (bx & 31) * 16;

    const int tid  = threadIdx.x;
    const int lane = tid & 31;
    const int w    = tid >> 5;
    const int g    = lane >> 2;
    const int tg   = lane & 3;
    const int r    = w & 3;
    const int q    = w >> 2;

    // ---- copy packed weights into smem ----
    {
        const uint4* wb = whp + (long)m * Gg * 128;
        for (int f = tid; f < 48 * 128; f += 512) {
            int cc = f >> 7, qq = f & 127;
            int gr = (cc >> 4) * Hh + j0 + (cc & 15);
            uint4 v = wb[(long)gr * 128 + qq];
            *reinterpret_cast<uint4*>(Wpk + cc * STW + qq * 4) = v;
        }
    }
    __syncthreads();

    const long hb  = (long)m * Rr * Hh;
    const long hb2 = (long)m * Rr * (Hh >> 1);
    const int  kq  = q * 64;                 // kw (k-pair) base for this warp
    int ar[4] = { r*32 + g, r*32 + g + 8, r*32 + 16 + g, r*32 + 24 + g };

    // biases (constant across steps), indexed by (u, jj)
    float b_r[2][2], b_z[2][2], b_n[2][2];
#pragma unroll
    for (int u = 0; u < 2; u++)
#pragma unroll
        for (int jj = 0; jj < 2; jj++) {
            int j = j0 + u * 8 + 2 * tg + jj;
            b_r[u][jj] = __ldg(&bhh[m * Gg + j]);
            b_z[u][jj] = __ldg(&bhh[m * Gg + Hh + j]);
            b_n[u][jj] = __ldg(&bhh[m * Gg + 2 * Hh + j]);
        }

    for (int t = 0; t < Ss; t++) {
        const float* hc = (t & 1) ? bufB : bufA;
        float*       hn = (t & 1) ? bufA : bufB;
        const uint2* pc = (t & 1) ? pakB : pakA;
        uint2*       pn = (t & 1) ? pakA : pakB;

        float c[2][6][4];
#pragma unroll
        for (int e = 0; e < 48; e++) (&c[0][0][0])[e] = 0.f;

        auto fetchA = [&](int i, uint2* d) {
            int kwb = kq + i * 8;
#pragma unroll
            for (int mt = 0; mt < 2; mt++) {
                d[mt*4+0] = __ldcg(&pc[hb2 + (long)ar[mt*2+0] * 256 + kwb + tg]);
                d[mt*4+1] = __ldcg(&pc[hb2 + (long)ar[mt*2+1] * 256 + kwb + tg]);
                d[mt*4+2] = __ldcg(&pc[hb2 + (long)ar[mt*2+0] * 256 + kwb + tg + 4]);
                d[mt*4+3] = __ldcg(&pc[hb2 + (long)ar[mt*2+1] * 256 + kwb + tg + 4]);
            }
        };
        auto mmaK16 = [&](int i, const uint2* A) {
            int kwb = kq + i * 8;
            uint32_t ahi[2][4], alo[2][4];
#pragma unroll
            for (int mt = 0; mt < 2; mt++)
#pragma unroll
                for (int s = 0; s < 4; s++) {
                    ahi[mt][s] = A[mt*4+s].x;
                    alo[mt][s] = A[mt*4+s].y;
                }
#pragma unroll
            for (int tI = 0; tI < 6; tI++) {
                int cc = tI * 8 + g;
                uint2 B0 = *reinterpret_cast<const uint2*>(Wpk + cc * STW + (kwb + tg) * 2);
                uint2 B1 = *reinterpret_cast<const uint2*>(Wpk + cc * STW + (kwb + tg + 4) * 2);
                uint32_t bh[2] = {B0.x, B1.x};
                uint32_t bl[2] = {B0.y, B1.y};
#pragma unroll
                for (int mt = 0; mt < 2; mt++) {
                    mma_bf16(c[mt][tI], ahi[mt], bh);
                    mma_bf16(c[mt][tI], ahi[mt], bl);
                    mma_bf16(c[mt][tI], alo[mt], bh);
                }
            }
        };

        uint2 Aa[8], Ab[8];
        fetchA(0, Aa);
#pragma unroll
        for (int i = 0; i < 8; i++) {
            uint2* cur = (i & 1) ? Ab : Aa;
            uint2* nxt = (i & 1) ? Aa : Ab;
            if (i < 7) fetchA(i + 1, nxt);
            mmaK16(i, cur);
        }

        // ---- reduce partials across K quarters ----
        if (q) {
            float* dst = part + (((q - 1) * 4 + r) * 32 + lane) * 48;
#pragma unroll
            for (int e = 0; e < 12; e++)
                *reinterpret_cast<float4*>(dst + e * 4) =
                    *reinterpret_cast<float4*>(&c[0][0][0] + e * 4);
        }
        __syncthreads();

        if (q == 0) {
#pragma unroll
            for (int qq = 0; qq < 3; qq++) {
                const float* src = part + ((qq * 4 + r) * 32 + lane) * 48;
#pragma unroll
                for (int e = 0; e < 48; e++) (&c[0][0][0])[e] += src[e];
            }
            // ---- epilogue: gates + h update ----
#pragma unroll
            for (int mt = 0; mt < 2; mt++)
#pragma unroll
            for (int rh = 0; rh < 2; rh++) {
                int row = r * 32 + mt * 16 + rh * 8 + g;
                int p = row >> 5, b = row & 31;
                long girow = (LAYER == 0)
                    ? ((long)(m * Ss + t) * Bb + b) * Gg
                    : ((long)((m * Pp + p) * Ss + t) * Bb + b) * Gg;
                long obase = (((long)(m * Pp + p) * Ss + t) * Bb + b) * Hh;
#pragma unroll
                for (int u = 0; u < 2; u++) {
                    int j = j0 + u * 8 + 2 * tg;
                    float2 gr2 = *reinterpret_cast<const float2*>(&gi[girow + j]);
                    float2 gz2 = *reinterpret_cast<const float2*>(&gi[girow + Hh + j]);
                    float2 gn2 = *reinterpret_cast<const float2*>(&gi[girow + 2 * Hh + j]);
                    float2 ho2 = __ldcg(reinterpret_cast<const float2*>(&hc[hb + (long)row * Hh + j]));
                    float hv[2];
#pragma unroll
                    for (int jj = 0; jj < 2; jj++) {
                        int qi = rh * 2 + jj;
                        float ghr = c[mt][0 + u][qi] + b_r[u][jj];
                        float ghz = c[mt][2 + u][qi] + b_z[u][jj];
                        float ghn = c[mt][4 + u][qi] + b_n[u][jj];
                        float gih = (jj == 0) ? gr2.x : gr2.y;
                        float giz = (jj == 0) ? gz2.x : gz2.y;
                        float gin = (jj == 0) ? gn2.x : gn2.y;
                        float hold = (jj == 0) ? ho2.x : ho2.y;
                        float rg = sigmoidf_(gih + ghr);
                        float zg = sigmoidf_(giz + ghz);
                        float ng = tanhf(gin + rg * ghn);
                        hv[jj] = (1.0f - zg) * ng + zg * hold;
                    }
                    __stcg(reinterpret_cast<float2*>(&hn[hb + (long)row * Hh + j]),
                           make_float2(hv[0], hv[1]));
                    __stcg(&pn[hb2 + (long)row * 256 + (j >> 1)], pack_hilo(hv[0], hv[1]));
                    float2 oa;
                    if (LAYER == 0) {
                        float2 dmv = *reinterpret_cast<const float2*>(&dm[obase + j]);
                        oa = make_float2(hv[0] * dmv.x, hv[1] * dmv.y);
                    } else {
                        oa = make_float2(fmaxf(hv[0], 0.f) + 0.01f * fminf(hv[0], 0.f),
                                         fmaxf(hv[1], 0.f) + 0.01f * fminf(hv[1], 0.f));
                    }
                    *reinterpret_cast<float2*>(&outact[obase + j]) = oa;
                }
            }
        }

        // ---- per-model grid barrier ----
        __syncthreads();
        if (tid == 0) {
            __threadfence();
            atomicAdd(&syncctr[m], 1u);
            unsigned target = 32u * (unsigned)(t + 1);
            volatile unsigned* vc = (volatile unsigned*)&syncctr[m];
            while (*vc < target) __nanosleep(64);
        }
        __syncthreads();
    }
}

// ---------------- mean / var ----------------
__global__ void meanvar_kernel(const float* __restrict__ preds,
                               float* __restrict__ out_mean, float* __restrict__ out_var)
{
    const int n = Ss * Bb * Oo;
    int idx = blockIdx.x * blockDim.x + threadIdx.x;
    if (idx >= n) return;
    float v[16];
    float s = 0.f;
#pragma unroll
    for (int mp = 0; mp < 16; mp++) {
        v[mp] = preds[(long)mp * n + idx];
        s += v[mp];
    }
    float mu = s * (1.0f / 16.0f);
    float qq = 0.f;
#pragma unroll
    for (int mp = 0; mp < 16; mp++) {
        float d = v[mp] - mu;
        qq += d * d;
    }
    out_mean[idx] = mu;
    out_var[idx]  = qq * (1.0f / 15.0f);
}

// ---------------- host launch ----------------
extern "C" void kernel_launch(void* const* d_in, const int* in_sizes, int n_in,
                              void* d_out, int out_size)
{
    const float* input  = (const float*)d_in[0];
    const float* hidden = (const float*)d_in[1];
    const float* w_ih0  = (const float*)d_in[2];
    const float* w_hh0  = (const float*)d_in[3];
    const float* b_ih0  = (const float*)d_in[4];
    const float* b_hh0  = (const float*)d_in[5];
    const float* w_ih1  = (const float*)d_in[6];
    const float* w_hh1  = (const float*)d_in[7];
    const float* b_ih1  = (const float*)d_in[8];
    const float* b_hh1  = (const float*)d_in[9];
    const float* lin_w  = (const float*)d_in[10];
    const float* lin_b  = (const float*)d_in[11];
    const float* dm     = (const float*)d_in[12];

    float* out = (float*)d_out;
    float* out_mean   = out;
    float* out_var    = out + (size_t)Ss * Bb * Oo;
    float* preds      = out + 2 * (size_t)Ss * Bb * Oo;
    float* hidden_out = preds + (size_t)Mm * Pp * Ss * Bb * Oo;

    float *gi0, *y0m, *gi1, *a1, *h0a, *h0b, *h1a, *h1b;
    uint2 *p0a, *p0b, *p1a, *p1b;
    uint4* whp;
    unsigned* syncp;
    cudaGetSymbolAddress((void**)&gi0, g_gi0);
    cudaGetSymbolAddress((void**)&y0m, g_y0m);
    cudaGetSymbolAddress((void**)&gi1, g_gi1);
    cudaGetSymbolAddress((void**)&a1,  g_a1);
    cudaGetSymbolAddress((void**)&h0a, g_h0a);
    cudaGetSymbolAddress((void**)&h0b, g_h0b);
    cudaGetSymbolAddress((void**)&h1a, g_h1a);
    cudaGetSymbolAddress((void**)&h1b, g_h1b);
    cudaGetSymbolAddress((void**)&p0a, g_hp0a);
    cudaGetSymbolAddress((void**)&p0b, g_hp0b);
    cudaGetSymbolAddress((void**)&p1a, g_hp1a);
    cudaGetSymbolAddress((void**)&p1b, g_hp1b);
    cudaGetSymbolAddress((void**)&whp, g_whhp);
    cudaGetSymbolAddress((void**)&syncp, g_sync);

    cudaFuncSetAttribute(gru_scan<0>, cudaFuncAttributeMaxDynamicSharedMemorySize, SCAN_SMEM_BYTES);
    cudaFuncSetAttribute(gru_scan<1>, cudaFuncAttributeMaxDynamicSharedMemorySize, SCAN_SMEM_BYTES);

    // 0) split+pack recurrent weights (bf16 hi/lo)
    {
        int n2 = 2 * Mm * Gg * (Hh / 2);
        split_pack_kernel<<<(n2 + 255) / 256, 256>>>(w_hh0, w_hh1, (uint2*)whp);
    }

    // 1) init hidden (fp32 + packed) + zero barrier counters
    {
        int n2 = Mm * Pp * Bb * (Hh / 2);
        init_hidden_kernel<<<(n2 + 255) / 256, 256>>>(hidden, h0a, h1a, p0a, p1a, syncp);
    }

    // 2) gi0 = input @ w_ih0^T + b_ih0  (TF32)
    {
        dim3 grid(Gg / 64, (Ss * Bb) / 128, Mm);
        gemm_tf32_bias<<<grid, 256>>>(input, 0L,
                                      w_ih0, (long)Gg * Ii,
                                      b_ih0, Gg,
                                      gi0, (long)Ss * Bb * Gg,
                                      Ss * Bb, Gg, Ii);
    }

    // 3) layer-0 persistent scan
    gru_scan<0><<<128, 512, SCAN_SMEM_BYTES>>>(h0a, h0b, p0a, p0b, gi0,
                                               whp, b_hh0, dm, y0m, syncp);

    // 4) gi1 = y0m @ w_ih1^T + b_ih1 (TF32)
    {
        dim3 grid(Gg / 64, (Pp * Ss * Bb) / 128, Mm);
        gemm_tf32_bias<<<grid, 256>>>(y0m, (long)Pp * Ss * Bb * Hh,
                                      w_ih1, (long)Gg * Hh,
                                      b_ih1, Gg,
                                      gi1, (long)Pp * Ss * Bb * Gg,
                                      Pp * Ss * Bb, Gg, Hh);
    }

    // 5) layer-1 persistent scan
    gru_scan<1><<<128, 512, SCAN_SMEM_BYTES>>>(h1a, h1b, p1a, p1b, gi1,
                                               whp + (long)Mm * Gg * 128, b_hh1,
                                               nullptr, a1, syncp + 4);

    // 6) preds = a1 @ lin_w^T + lin_b (TF32)
    {
        dim3 grid(Oo / 64, (Pp * Ss * Bb) / 128, Mm);
        gemm_tf32_bias<<<grid, 256>>>(a1, (long)Pp * Ss * Bb * Hh,
                                      lin_w, (long)Oo * Hh,
                                      lin_b, Oo,
                                      preds, (long)Pp * Ss * Bb * Oo,
                                      Pp * Ss * Bb, Oo, Hh);
    }

    // 7) mean / var
    meanvar_kernel<<<(Ss * Bb * Oo + 255) / 256, 256>>>(preds, out_mean, out_var);

    // 8) hidden out (256 steps even -> final h in 'a' buffers)
    hidden_out_kernel<<<(Mm*Pp*Bb*Hh + 255) / 256, 256>>>(h0a, h1a, hidden_out);
}

// round 6
// speedup vs baseline: 1.4516x; 1.1742x over previous
#include <cuda_runtime.h>
#include <cuda_bf16.h>
#include <math.h>
#include <stdint.h>

// Problem constants
#define Mm 4
#define Pp 4
#define Ll 2
#define Ss 256
#define Bb 32
#define Ii 256
#define Hh 512
#define Oo 256
#define Gg (3*Hh)     // 1536
#define Rr (Pp*Bb)    // 128 rows per model in the recurrence

#define STW 524       // smem weight row stride in 32-bit words (per gate-col)
// weights 48*STW words + partials 8*24*32 floats
#define SCAN_SMEM_BYTES (48*STW*4 + 8*24*32*4)    // 100608 + 24576 = 125184

// ---------------- scratch (device globals; no allocation) ----------------
__device__ float g_gi0[(size_t)Mm*Ss*Bb*Gg];
__device__ float g_y0m[(size_t)Mm*Pp*Ss*Bb*Hh];
__device__ float g_gi1[(size_t)Mm*Pp*Ss*Bb*Gg];
__device__ float g_a1 [(size_t)Mm*Pp*Ss*Bb*Hh];
__device__ float g_h0a[Mm*Rr*Hh];
__device__ float g_h0b[Mm*Rr*Hh];
__device__ float g_h1a[Mm*Rr*Hh];
__device__ float g_h1b[Mm*Rr*Hh];
// packed bf16 (hi,lo) versions of h, double buffered, per layer
__device__ uint2 g_hp0a[Mm*Rr*(Hh/2)];
__device__ uint2 g_hp0b[Mm*Rr*(Hh/2)];
__device__ uint2 g_hp1a[Mm*Rr*(Hh/2)];
__device__ uint2 g_hp1b[Mm*Rr*(Hh/2)];
// packed bf16 (hi,lo) recurrent weights: [layer][M][3H][Hh/2] as uint2 (uint4-aligned)
__device__ uint4 g_whhp[2 * Mm * Gg * 128];
__device__ unsigned g_sync[8];

// ---------------- helpers ----------------
__device__ __forceinline__ float tf32r(float x) {
    uint32_t u;
    asm("cvt.rna.tf32.f32 %0, %1;" : "=r"(u) : "f"(x));
    return __uint_as_float(u);
}

__device__ __forceinline__ void mma_tf32(float c[4], const uint32_t a[4], const uint32_t b[2]) {
    asm volatile(
        "mma.sync.aligned.m16n8k8.row.col.f32.tf32.tf32.f32 "
        "{%0,%1,%2,%3},{%4,%5,%6,%7},{%8,%9},{%0,%1,%2,%3};"
        : "+f"(c[0]), "+f"(c[1]), "+f"(c[2]), "+f"(c[3])
        : "r"(a[0]), "r"(a[1]), "r"(a[2]), "r"(a[3]), "r"(b[0]), "r"(b[1]));
}

__device__ __forceinline__ void mma_bf16(float c[4], const uint32_t a[4], const uint32_t b[2]) {
    asm volatile(
        "mma.sync.aligned.m16n8k16.row.col.f32.bf16.bf16.f32 "
        "{%0,%1,%2,%3},{%4,%5,%6,%7},{%8,%9},{%0,%1,%2,%3};"
        : "+f"(c[0]), "+f"(c[1]), "+f"(c[2]), "+f"(c[3])
        : "r"(a[0]), "r"(a[1]), "r"(a[2]), "r"(a[3]), "r"(b[0]), "r"(b[1]));
}

__device__ __forceinline__ float sigmoidf_(float x) { return 1.0f / (1.0f + expf(-x)); }

// pack two fp32 into (bf16-hi word, bf16-lo word)
__device__ __forceinline__ uint2 pack_hilo(float x0, float x1) {
    __nv_bfloat162 hi = __floats2bfloat162_rn(x0, x1);
    float l0 = x0 - __bfloat162float(hi.x);
    float l1 = x1 - __bfloat162float(hi.y);
    __nv_bfloat162 lo = __floats2bfloat162_rn(l0, l1);
    uint2 r;
    r.x = *reinterpret_cast<unsigned*>(&hi);
    r.y = *reinterpret_cast<unsigned*>(&lo);
    return r;
}

// ---------------- init hidden (fp32 + packed) + zero sync ----------------
__global__ void init_hidden_kernel(const float* __restrict__ hidden,
                                   float* __restrict__ h0, float* __restrict__ h1,
                                   uint2* __restrict__ p0, uint2* __restrict__ p1,
                                   unsigned* __restrict__ sync)
{
    int idx = blockIdx.x * blockDim.x + threadIdx.x;
    if (blockIdx.x == 0 && threadIdx.x < 8) sync[threadIdx.x] = 0u;
    const int n2 = Mm*Pp*Bb*(Hh/2);
    if (idx >= n2) return;
    int mp  = idx / (Bb*(Hh/2));
    int rem = idx % (Bb*(Hh/2));
    float2 v0 = *reinterpret_cast<const float2*>(&hidden[((size_t)mp*Ll + 0)*Bb*Hh + rem*2]);
    float2 v1 = *reinterpret_cast<const float2*>(&hidden[((size_t)mp*Ll + 1)*Bb*Hh + rem*2]);
    *reinterpret_cast<float2*>(&h0[(size_t)mp*Bb*Hh + rem*2]) = v0;
    *reinterpret_cast<float2*>(&h1[(size_t)mp*Bb*Hh + rem*2]) = v1;
    p0[(size_t)mp*Bb*(Hh/2) + rem] = pack_hilo(v0.x, v0.y);
    p1[(size_t)mp*Bb*(Hh/2) + rem] = pack_hilo(v1.x, v1.y);
}

__global__ void hidden_out_kernel(const float* __restrict__ h0, const float* __restrict__ h1,
                                  float* __restrict__ out)
{
    int idx = blockIdx.x * blockDim.x + threadIdx.x;
    const int n = Mm*Pp*Bb*Hh;
    if (idx >= n) return;
    int mp  = idx / (Bb*Hh);
    int rem = idx % (Bb*Hh);
    out[((size_t)mp*Ll + 0)*Bb*Hh + rem] = h0[idx];
    out[((size_t)mp*Ll + 1)*Bb*Hh + rem] = h1[idx];
}

// ---------------- split weights into packed bf16 hi/lo words ----------------
__global__ void split_pack_kernel(const float* __restrict__ w0, const float* __restrict__ w1,
                                  uint2* __restrict__ outp)
{
    const int n = Mm * Gg * (Hh/2);
    int idx = blockIdx.x * blockDim.x + threadIdx.x;
    if (idx >= 2 * n) return;
    const float* src = (idx < n) ? w0 : w1;
    int within = (idx < n) ? idx : idx - n;
    float2 x = *reinterpret_cast<const float2*>(src + (size_t)within * 2);
    outp[idx] = pack_hilo(x.x, x.y);
}

// ================= TF32 tensor-core GEMM with bias (feedforward) =================
__global__ __launch_bounds__(256) void gemm_tf32_bias(
    const float* __restrict__ A, long aStride,
    const float* __restrict__ W, long wStride,
    const float* __restrict__ bias, int bStride,
    float* __restrict__ C, long cStride,
    int rows, int N, int K)
{
    const int batch = blockIdx.z;
    A    += (long)batch * aStride;
    W    += (long)batch * wStride;
    bias += (long)batch * bStride;
    C    += (long)batch * cStride;

    const int r0 = blockIdx.y * 128;
    const int n0 = blockIdx.x * 64;

    __shared__ float As[128][36];
    __shared__ float Bs[64][36];

    const int tid  = threadIdx.x;
    const int lane = tid & 31;
    const int w    = tid >> 5;
    const int wr   = w >> 1;
    const int wc   = w & 1;
    const int gID  = lane >> 2;
    const int tig  = lane & 3;

    float c[2][4][4];
#pragma unroll
    for (int mi = 0; mi < 2; mi++)
#pragma unroll
        for (int ni = 0; ni < 4; ni++)
#pragma unroll
            for (int q = 0; q < 4; q++) c[mi][ni][q] = 0.f;

    for (int k0 = 0; k0 < K; k0 += 32) {
#pragma unroll
        for (int l = 0; l < 4; l++) {
            int f = tid + l * 256;
            int row = f >> 3;
            int kg  = f & 7;
            float4 v = *reinterpret_cast<const float4*>(&A[(long)(r0 + row) * K + k0 + kg * 4]);
            float4 t;
            t.x = tf32r(v.x); t.y = tf32r(v.y); t.z = tf32r(v.z); t.w = tf32r(v.w);
            *reinterpret_cast<float4*>(&As[row][kg * 4]) = t;
        }
#pragma unroll
        for (int l = 0; l < 2; l++) {
            int f = tid + l * 256;
            int col = f >> 3;
            int kg  = f & 7;
            float4 v = *reinterpret_cast<const float4*>(&W[(long)(n0 + col) * K + k0 + kg * 4]);
            float4 t;
            t.x = tf32r(v.x); t.y = tf32r(v.y); t.z = tf32r(v.z); t.w = tf32r(v.w);
            *reinterpret_cast<float4*>(&Bs[col][kg * 4]) = t;
        }
        __syncthreads();

#pragma unroll
        for (int k8 = 0; k8 < 4; k8++) {
            const int kb = k8 * 8;
            uint32_t af[2][4];
#pragma unroll
            for (int mi = 0; mi < 2; mi++) {
                int rb = wr * 32 + mi * 16 + gID;
                af[mi][0] = __float_as_uint(As[rb    ][kb + tig]);
                af[mi][1] = __float_as_uint(As[rb + 8][kb + tig]);
                af[mi][2] = __float_as_uint(As[rb    ][kb + 4 + tig]);
                af[mi][3] = __float_as_uint(As[rb + 8][kb + 4 + tig]);
            }
            uint32_t bf[4][2];
#pragma unroll
            for (int ni = 0; ni < 4; ni++) {
                int cb = wc * 32 + ni * 8 + gID;
                bf[ni][0] = __float_as_uint(Bs[cb][kb + tig]);
                bf[ni][1] = __float_as_uint(Bs[cb][kb + 4 + tig]);
            }
#pragma unroll
            for (int mi = 0; mi < 2; mi++)
#pragma unroll
                for (int ni = 0; ni < 4; ni++)
                    mma_tf32(c[mi][ni], af[mi], bf[ni]);
        }
        __syncthreads();
    }

#pragma unroll
    for (int mi = 0; mi < 2; mi++) {
#pragma unroll
        for (int ni = 0; ni < 4; ni++) {
            int row = r0 + wr * 32 + mi * 16 + gID;
            int col = n0 + wc * 32 + ni * 8 + 2 * tig;
            float b0 = bias[col], b1 = bias[col + 1];
            float2 v0 = make_float2(c[mi][ni][0] + b0, c[mi][ni][1] + b1);
            float2 v1 = make_float2(c[mi][ni][2] + b0, c[mi][ni][3] + b1);
            *reinterpret_cast<float2*>(&C[(long)row * N + col]) = v0;
            *reinterpret_cast<float2*>(&C[(long)(row + 8) * N + col]) = v1;
        }
    }
}

// ================= persistent GRU scan: bf16-3 mma, conflict-free reduction =================
// grid = 128 blocks (m = bx>>5, j0 = (bx&31)*16), 512 threads = 16 warps.
// warp w: row-group r = w&7 (16 rows, one m16 tile), K-half q = w>>3 (256 k).
// q==1 warps dump partials (transposed, conflict-free); q==0 warps reduce + epilogue.
template<int LAYER>
__global__ __launch_bounds__(512, 1) void gru_scan(
    float* __restrict__ bufA, float* __restrict__ bufB,
    uint2* __restrict__ pakA, uint2* __restrict__ pakB,
    const float* __restrict__ gi,
    const uint4* __restrict__ whp,   // layer base already applied
    const float* __restrict__ bhh,
    const float* __restrict__ dm,
    float* __restrict__ outact,
    unsigned* __restrict__ syncctr)
{
    extern __shared__ unsigned smw[];
    unsigned* Wpk = smw;                          // 48 x STW words
    float* part = (float*)(smw + 48 * STW);       // [8 rowgrp][24 elems][32 lanes]

    const int bx = blockIdx.x;
    const int m  = bx >> 5;
    const int j0 = (bx & 31) * 16;

    const int tid  = threadIdx.x;
    const int lane = tid & 31;
    const int w    = tid >> 5;
    const int g    = lane >> 2;
    const int tg   = lane & 3;
    const int r    = w & 7;      // row group (16 rows)
    const int q    = w >> 3;     // K half

    // ---- copy packed weights into smem ----
    {
        const uint4* wb = whp + (long)m * Gg * 128;
        for (int f = tid; f < 48 * 128; f += 512) {
            int cc = f >> 7, qq = f & 127;
            int gr = (cc >> 4) * Hh + j0 + (cc & 15);
            uint4 v = wb[(long)gr * 128 + qq];
            *reinterpret_cast<uint4*>(Wpk + cc * STW + qq * 4) = v;
        }
    }
    __syncthreads();

    const long hb  = (long)m * Rr * Hh;
    const long hb2 = (long)m * Rr * (Hh >> 1);
    const int  kq  = q * 128;                 // k-pair base for this warp (half = 128 pairs)
    const int  ar0 = r * 16 + g;
    const int  ar1 = r * 16 + 8 + g;

    // biases (constant across steps), indexed by (u, jj)
    float b_r[2][2], b_z[2][2], b_n[2][2];
#pragma unroll
    for (int u = 0; u < 2; u++)
#pragma unroll
        for (int jj = 0; jj < 2; jj++) {
            int j = j0 + u * 8 + 2 * tg + jj;
            b_r[u][jj] = __ldg(&bhh[m * Gg + j]);
            b_z[u][jj] = __ldg(&bhh[m * Gg + Hh + j]);
            b_n[u][jj] = __ldg(&bhh[m * Gg + 2 * Hh + j]);
        }

    for (int t = 0; t < Ss; t++) {
        const float* hc = (t & 1) ? bufB : bufA;
        float*       hn = (t & 1) ? bufA : bufB;
        const uint2* pc = (t & 1) ? pakB : pakA;
        uint2*       pn = (t & 1) ? pakA : pakB;

        // ---- early prefetch of epilogue operands (q==0 warps only) ----
        float2 gr2[2][2], gz2[2][2], gn2[2][2], ho2[2][2];
        if (q == 0) {
#pragma unroll
            for (int rh = 0; rh < 2; rh++) {
                int row = r * 16 + rh * 8 + g;
                int p = row >> 5, b = row & 31;
                long girow = (LAYER == 0)
                    ? ((long)(m * Ss + t) * Bb + b) * Gg
                    : ((long)((m * Pp + p) * Ss + t) * Bb + b) * Gg;
#pragma unroll
                for (int u = 0; u < 2; u++) {
                    int j = j0 + u * 8 + 2 * tg;
                    gr2[rh][u] = __ldcg(reinterpret_cast<const float2*>(&gi[girow + j]));
                    gz2[rh][u] = __ldcg(reinterpret_cast<const float2*>(&gi[girow + Hh + j]));
                    gn2[rh][u] = __ldcg(reinterpret_cast<const float2*>(&gi[girow + 2 * Hh + j]));
                    ho2[rh][u] = __ldcg(reinterpret_cast<const float2*>(&hc[hb + (long)row * Hh + j]));
                }
            }
        }

        float c[6][4];
#pragma unroll
        for (int e = 0; e < 24; e++) (&c[0][0])[e] = 0.f;

        auto fetchA = [&](int i, uint2* d) {
            int kwb = kq + i * 8;
            d[0] = __ldcg(&pc[hb2 + (long)ar0 * 256 + kwb + tg]);
            d[1] = __ldcg(&pc[hb2 + (long)ar1 * 256 + kwb + tg]);
            d[2] = __ldcg(&pc[hb2 + (long)ar0 * 256 + kwb + tg + 4]);
            d[3] = __ldcg(&pc[hb2 + (long)ar1 * 256 + kwb + tg + 4]);
        };
        auto mmaK16 = [&](int i, const uint2* A) {
            int kwb = kq + i * 8;
            uint32_t ahi[4] = {A[0].x, A[1].x, A[2].x, A[3].x};
            uint32_t alo[4] = {A[0].y, A[1].y, A[2].y, A[3].y};
#pragma unroll
            for (int tI = 0; tI < 6; tI++) {
                int cc = tI * 8 + g;
                uint2 B0 = *reinterpret_cast<const uint2*>(Wpk + cc * STW + (kwb + tg) * 2);
                uint2 B1 = *reinterpret_cast<const uint2*>(Wpk + cc * STW + (kwb + tg + 4) * 2);
                uint32_t bh[2] = {B0.x, B1.x};
                uint32_t bl[2] = {B0.y, B1.y};
                mma_bf16(c[tI], ahi, bh);
                mma_bf16(c[tI], ahi, bl);
                mma_bf16(c[tI], alo, bh);
            }
        };

        uint2 Aa[4], Ab[4];
        fetchA(0, Aa);
#pragma unroll
        for (int i = 0; i < 16; i++) {
            uint2* cur = (i & 1) ? Ab : Aa;
            uint2* nxt = (i & 1) ? Aa : Ab;
            if (i < 15) fetchA(i + 1, nxt);
            mmaK16(i, cur);
        }

        // ---- reduce partials across the two K halves (conflict-free layout) ----
        if (q == 1) {
            float* dst = part + (r * 24) * 32 + lane;
#pragma unroll
            for (int e = 0; e < 24; e++)
                dst[e * 32] = (&c[0][0])[e];
        }
        __syncthreads();

        if (q == 0) {
            const float* src = part + (r * 24) * 32 + lane;
#pragma unroll
            for (int e = 0; e < 24; e++)
                (&c[0][0])[e] += src[e * 32];

            // ---- epilogue: gates + h update ----
#pragma unroll
            for (int rh = 0; rh < 2; rh++) {
                int row = r * 16 + rh * 8 + g;
                int p = row >> 5, b = row & 31;
                long obase = (((long)(m * Pp + p) * Ss + t) * Bb + b) * Hh;
#pragma unroll
                for (int u = 0; u < 2; u++) {
                    int j = j0 + u * 8 + 2 * tg;
                    float hv[2];
#pragma unroll
                    for (int jj = 0; jj < 2; jj++) {
                        int qi = rh * 2 + jj;
                        float ghr = c[0 + u][qi] + b_r[u][jj];
                        float ghz = c[2 + u][qi] + b_z[u][jj];
                        float ghn = c[4 + u][qi] + b_n[u][jj];
                        float gih = (jj == 0) ? gr2[rh][u].x : gr2[rh][u].y;
                        float giz = (jj == 0) ? gz2[rh][u].x : gz2[rh][u].y;
                        float gin = (jj == 0) ? gn2[rh][u].x : gn2[rh][u].y;
                        float hold = (jj == 0) ? ho2[rh][u].x : ho2[rh][u].y;
                        float rg = sigmoidf_(gih + ghr);
                        float zg = sigmoidf_(giz + ghz);
                        float ng = tanhf(gin + rg * ghn);
                        hv[jj] = (1.0f - zg) * ng + zg * hold;
                    }
                    __stcg(reinterpret_cast<float2*>(&hn[hb + (long)row * Hh + j]),
                           make_float2(hv[0], hv[1]));
                    __stcg(&pn[hb2 + (long)row * 256 + (j >> 1)], pack_hilo(hv[0], hv[1]));
                    float2 oa;
                    if (LAYER == 0) {
                        float2 dmv = __ldcg(reinterpret_cast<const float2*>(&dm[obase + j]));
                        oa = make_float2(hv[0] * dmv.x, hv[1] * dmv.y);
                    } else {
                        oa = make_float2(fmaxf(hv[0], 0.f) + 0.01f * fminf(hv[0], 0.f),
                                         fmaxf(hv[1], 0.f) + 0.01f * fminf(hv[1], 0.f));
                    }
                    __stcg(reinterpret_cast<float2*>(&outact[obase + j]), oa);
                }
            }
        }

        // ---- per-model grid barrier ----
        __syncthreads();
        if (tid == 0) {
            __threadfence();
            atomicAdd(&syncctr[m], 1u);
            unsigned target = 32u * (unsigned)(t + 1);
            volatile unsigned* vc = (volatile unsigned*)&syncctr[m];
            while (*vc < target) __nanosleep(32);
        }
        __syncthreads();
    }
}

// ---------------- mean / var ----------------
__global__ void meanvar_kernel(const float* __restrict__ preds,
                               float* __restrict__ out_mean, float* __restrict__ out_var)
{
    const int n = Ss * Bb * Oo;
    int idx = blockIdx.x * blockDim.x + threadIdx.x;
    if (idx >= n) return;
    float v[16];
    float s = 0.f;
#pragma unroll
    for (int mp = 0; mp < 16; mp++) {
        v[mp] = preds[(long)mp * n + idx];
        s += v[mp];
    }
    float mu = s * (1.0f / 16.0f);
    float qq = 0.f;
#pragma unroll
    for (int mp = 0; mp < 16; mp++) {
        float d = v[mp] - mu;
        qq += d * d;
    }
    out_mean[idx] = mu;
    out_var[idx]  = qq * (1.0f / 15.0f);
}

// ---------------- host launch ----------------
extern "C" void kernel_launch(void* const* d_in, const int* in_sizes, int n_in,
                              void* d_out, int out_size)
{
    const float* input  = (const float*)d_in[0];
    const float* hidden = (const float*)d_in[1];
    const float* w_ih0  = (const float*)d_in[2];
    const float* w_hh0  = (const float*)d_in[3];
    const float* b_ih0  = (const float*)d_in[4];
    const float* b_hh0  = (const float*)d_in[5];
    const float* w_ih1  = (const float*)d_in[6];
    const float* w_hh1  = (const float*)d_in[7];
    const float* b_ih1  = (const float*)d_in[8];
    const float* b_hh1  = (const float*)d_in[9];
    const float* lin_w  = (const float*)d_in[10];
    const float* lin_b  = (const float*)d_in[11];
    const float* dm     = (const float*)d_in[12];

    float* out = (float*)d_out;
    float* out_mean   = out;
    float* out_var    = out + (size_t)Ss * Bb * Oo;
    float* preds      = out + 2 * (size_t)Ss * Bb * Oo;
    float* hidden_out = preds + (size_t)Mm * Pp * Ss * Bb * Oo;

    float *gi0, *y0m, *gi1, *a1, *h0a, *h0b, *h1a, *h1b;
    uint2 *p0a, *p0b, *p1a, *p1b;
    uint4* whp;
    unsigned* syncp;
    cudaGetSymbolAddress((void**)&gi0, g_gi0);
    cudaGetSymbolAddress((void**)&y0m, g_y0m);
    cudaGetSymbolAddress((void**)&gi1, g_gi1);
    cudaGetSymbolAddress((void**)&a1,  g_a1);
    cudaGetSymbolAddress((void**)&h0a, g_h0a);
    cudaGetSymbolAddress((void**)&h0b, g_h0b);
    cudaGetSymbolAddress((void**)&h1a, g_h1a);
    cudaGetSymbolAddress((void**)&h1b, g_h1b);
    cudaGetSymbolAddress((void**)&p0a, g_hp0a);
    cudaGetSymbolAddress((void**)&p0b, g_hp0b);
    cudaGetSymbolAddress((void**)&p1a, g_hp1a);
    cudaGetSymbolAddress((void**)&p1b, g_hp1b);
    cudaGetSymbolAddress((void**)&whp, g_whhp);
    cudaGetSymbolAddress((void**)&syncp, g_sync);

    cudaFuncSetAttribute(gru_scan<0>, cudaFuncAttributeMaxDynamicSharedMemorySize, SCAN_SMEM_BYTES);
    cudaFuncSetAttribute(gru_scan<1>, cudaFuncAttributeMaxDynamicSharedMemorySize, SCAN_SMEM_BYTES);

    // 0) split+pack recurrent weights (bf16 hi/lo)
    {
        int n2 = 2 * Mm * Gg * (Hh / 2);
        split_pack_kernel<<<(n2 + 255) / 256, 256>>>(w_hh0, w_hh1, (uint2*)whp);
    }

    // 1) init hidden (fp32 + packed) + zero barrier counters
    {
        int n2 = Mm * Pp * Bb * (Hh / 2);
        init_hidden_kernel<<<(n2 + 255) / 256, 256>>>(hidden, h0a, h1a, p0a, p1a, syncp);
    }

    // 2) gi0 = input @ w_ih0^T + b_ih0  (TF32)
    {
        dim3 grid(Gg / 64, (Ss * Bb) / 128, Mm);
        gemm_tf32_bias<<<grid, 256>>>(input, 0L,
                                      w_ih0, (long)Gg * Ii,
                                      b_ih0, Gg,
                                      gi0, (long)Ss * Bb * Gg,
                                      Ss * Bb, Gg, Ii);
    }

    // 3) layer-0 persistent scan
    gru_scan<0><<<128, 512, SCAN_SMEM_BYTES>>>(h0a, h0b, p0a, p0b, gi0,
                                               whp, b_hh0, dm, y0m, syncp);

    // 4) gi1 = y0m @ w_ih1^T + b_ih1 (TF32)
    {
        dim3 grid(Gg / 64, (Pp * Ss * Bb) / 128, Mm);
        gemm_tf32_bias<<<grid, 256>>>(y0m, (long)Pp * Ss * Bb * Hh,
                                      w_ih1, (long)Gg * Hh,
                                      b_ih1, Gg,
                                      gi1, (long)Pp * Ss * Bb * Gg,
                                      Pp * Ss * Bb, Gg, Hh);
    }

    // 5) layer-1 persistent scan
    gru_scan<1><<<128, 512, SCAN_SMEM_BYTES>>>(h1a, h1b, p1a, p1b, gi1,
                                               whp + (long)Mm * Gg * 128, b_hh1,
                                               nullptr, a1, syncp + 4);

    // 6) preds = a1 @ lin_w^T + lin_b (TF32)
    {
        dim3 grid(Oo / 64, (Pp * Ss * Bb) / 128, Mm);
        gemm_tf32_bias<<<grid, 256>>>(a1, (long)Pp * Ss * Bb * Hh,
                                      lin_w, (long)Oo * Hh,
                                      lin_b, Oo,
                                      preds, (long)Pp * Ss * Bb * Oo,
                                      Pp * Ss * Bb, Oo, Hh);
    }

    // 7) mean / var
    meanvar_kernel<<<(Ss * Bb * Oo + 255) / 256, 256>>>(preds, out_mean, out_var);

    // 8) hidden out (256 steps even -> final h in 'a' buffers)
    hidden_out_kernel<<<(Mm*Pp*Bb*Hh + 255) / 256, 256>>>(h0a, h1a, hidden_out);
}

// round 7
// speedup vs baseline: 1.9501x; 1.3434x over previous
#include <cuda_runtime.h>
#include <cuda_bf16.h>
#include <math.h>
#include <stdint.h>

// Problem constants
#define Mm 4
#define Pp 4
#define Ll 2
#define Ss 256
#define Bb 32
#define Ii 256
#define Hh 512
#define Oo 256
#define Gg (3*Hh)     // 1536
#define Rr (Pp*Bb)    // 128 rows per model in the recurrence

#define WSTRIDE 528                         // smem words per gate-col row (512 + 16 pad)
#define SCAN_SMEM_BYTES (48*WSTRIDE*4)      // 101376

// ---------------- scratch (device globals; no allocation) ----------------
__device__ float g_gi0[(size_t)Mm*Ss*Bb*Gg];
__device__ float g_y0m[(size_t)Mm*Pp*Ss*Bb*Hh];
__device__ float g_gi1[(size_t)Mm*Pp*Ss*Bb*Gg];
__device__ float g_a1 [(size_t)Mm*Pp*Ss*Bb*Hh];
__device__ float g_h0a[Mm*Rr*Hh];
__device__ float g_h0b[Mm*Rr*Hh];
__device__ float g_h1a[Mm*Rr*Hh];
__device__ float g_h1b[Mm*Rr*Hh];
// packed bf16 (hi,lo) h, PERMUTED fragment layout, double buffered (uint4 for 16B align)
__device__ uint4 g_hp0a[Mm*Rr*128];
__device__ uint4 g_hp0b[Mm*Rr*128];
__device__ uint4 g_hp1a[Mm*Rr*128];
__device__ uint4 g_hp1b[Mm*Rr*128];
// packed bf16 (hi,lo) recurrent weights: [layer][M][3H][Hh/2] pairs as uint4
__device__ uint4 g_whhp[2 * Mm * Gg * 128];
__device__ unsigned g_sync[8];

// ---------------- helpers ----------------
__device__ __forceinline__ float tf32r(float x) {
    uint32_t u;
    asm("cvt.rna.tf32.f32 %0, %1;" : "=r"(u) : "f"(x));
    return __uint_as_float(u);
}

__device__ __forceinline__ void mma_tf32(float c[4], const uint32_t a[4], const uint32_t b[2]) {
    asm volatile(
        "mma.sync.aligned.m16n8k8.row.col.f32.tf32.tf32.f32 "
        "{%0,%1,%2,%3},{%4,%5,%6,%7},{%8,%9},{%0,%1,%2,%3};"
        : "+f"(c[0]), "+f"(c[1]), "+f"(c[2]), "+f"(c[3])
        : "r"(a[0]), "r"(a[1]), "r"(a[2]), "r"(a[3]), "r"(b[0]), "r"(b[1]));
}

__device__ __forceinline__ void mma_bf16(float c[4], const uint32_t a[4], const uint32_t b[2]) {
    asm volatile(
        "mma.sync.aligned.m16n8k16.row.col.f32.bf16.bf16.f32 "
        "{%0,%1,%2,%3},{%4,%5,%6,%7},{%8,%9},{%0,%1,%2,%3};"
        : "+f"(c[0]), "+f"(c[1]), "+f"(c[2]), "+f"(c[3])
        : "r"(a[0]), "r"(a[1]), "r"(a[2]), "r"(a[3]), "r"(b[0]), "r"(b[1]));
}

__device__ __forceinline__ float sigmoidf_(float x) { return 1.0f / (1.0f + expf(-x)); }

// pack two fp32 into (bf16-hi word, bf16-lo word)
__device__ __forceinline__ uint2 pack_hilo(float x0, float x1) {
    __nv_bfloat162 hi = __floats2bfloat162_rn(x0, x1);
    float l0 = x0 - __bfloat162float(hi.x);
    float l1 = x1 - __bfloat162float(hi.y);
    __nv_bfloat162 lo = __floats2bfloat162_rn(l0, l1);
    uint2 r;
    r.x = *reinterpret_cast<unsigned*>(&hi);
    r.y = *reinterpret_cast<unsigned*>(&lo);
    return r;
}

// fragment permutation of k-pair index (uint2 units): groups of 8 k-pairs so that
// (kp=base+tg, kp=base+tg+4) land adjacent -> one 128-bit load per fragment pair
__device__ __forceinline__ int permkp(int kp) {
    return (kp >> 3) * 8 + (kp & 3) * 2 + ((kp >> 2) & 1);
}

// ---------------- init hidden (fp32 + permuted packed) + zero sync ----------------
__global__ void init_hidden_kernel(const float* __restrict__ hidden,
                                   float* __restrict__ h0, float* __restrict__ h1,
                                   uint2* __restrict__ p0, uint2* __restrict__ p1,
                                   unsigned* __restrict__ sync)
{
    int idx = blockIdx.x * blockDim.x + threadIdx.x;
    if (blockIdx.x == 0 && threadIdx.x < 8) sync[threadIdx.x] = 0u;
    const int n2 = Mm*Pp*Bb*256;
    if (idx >= n2) return;
    int mp  = idx / (Bb*256);
    int rem = idx % (Bb*256);
    int b  = rem >> 8;
    int kp = rem & 255;
    float2 v0 = *reinterpret_cast<const float2*>(&hidden[((size_t)mp*Ll + 0)*Bb*Hh + b*Hh + 2*kp]);
    float2 v1 = *reinterpret_cast<const float2*>(&hidden[((size_t)mp*Ll + 1)*Bb*Hh + b*Hh + 2*kp]);
    *reinterpret_cast<float2*>(&h0[((size_t)mp*Bb + b)*Hh + 2*kp]) = v0;
    *reinterpret_cast<float2*>(&h1[((size_t)mp*Bb + b)*Hh + 2*kp]) = v1;
    p0[((size_t)mp*Bb + b)*256 + permkp(kp)] = pack_hilo(v0.x, v0.y);
    p1[((size_t)mp*Bb + b)*256 + permkp(kp)] = pack_hilo(v1.x, v1.y);
}

__global__ void hidden_out_kernel(const float* __restrict__ h0, const float* __restrict__ h1,
                                  float* __restrict__ out)
{
    int idx = blockIdx.x * blockDim.x + threadIdx.x;
    const int n = Mm*Pp*Bb*Hh;
    if (idx >= n) return;
    int mp  = idx / (Bb*Hh);
    int rem = idx % (Bb*Hh);
    out[((size_t)mp*Ll + 0)*Bb*Hh + rem] = h0[idx];
    out[((size_t)mp*Ll + 1)*Bb*Hh + rem] = h1[idx];
}

// ---------------- split weights into packed bf16 hi/lo words ----------------
__global__ void split_pack_kernel(const float* __restrict__ w0, const float* __restrict__ w1,
                                  uint2* __restrict__ outp)
{
    const int n = Mm * Gg * (Hh/2);
    int idx = blockIdx.x * blockDim.x + threadIdx.x;
    if (idx >= 2 * n) return;
    const float* src = (idx < n) ? w0 : w1;
    int within = (idx < n) ? idx : idx - n;
    float2 x = *reinterpret_cast<const float2*>(src + (size_t)within * 2);
    outp[idx] = pack_hilo(x.x, x.y);
}

// ================= TF32 tensor-core GEMM with bias (feedforward) =================
__global__ __launch_bounds__(256) void gemm_tf32_bias(
    const float* __restrict__ A, long aStride,
    const float* __restrict__ W, long wStride,
    const float* __restrict__ bias, int bStride,
    float* __restrict__ C, long cStride,
    int rows, int N, int K)
{
    const int batch = blockIdx.z;
    A    += (long)batch * aStride;
    W    += (long)batch * wStride;
    bias += (long)batch * bStride;
    C    += (long)batch * cStride;

    const int r0 = blockIdx.y * 128;
    const int n0 = blockIdx.x * 64;

    __shared__ float As[128][36];
    __shared__ float Bs[64][36];

    const int tid  = threadIdx.x;
    const int lane = tid & 31;
    const int w    = tid >> 5;
    const int wr   = w >> 1;
    const int wc   = w & 1;
    const int gID  = lane >> 2;
    const int tig  = lane & 3;

    float c[2][4][4];
#pragma unroll
    for (int mi = 0; mi < 2; mi++)
#pragma unroll
        for (int ni = 0; ni < 4; ni++)
#pragma unroll
            for (int q = 0; q < 4; q++) c[mi][ni][q] = 0.f;

    for (int k0 = 0; k0 < K; k0 += 32) {
#pragma unroll
        for (int l = 0; l < 4; l++) {
            int f = tid + l * 256;
            int row = f >> 3;
            int kg  = f & 7;
            float4 v = *reinterpret_cast<const float4*>(&A[(long)(r0 + row) * K + k0 + kg * 4]);
            float4 t;
            t.x = tf32r(v.x); t.y = tf32r(v.y); t.z = tf32r(v.z); t.w = tf32r(v.w);
            *reinterpret_cast<float4*>(&As[row][kg * 4]) = t;
        }
#pragma unroll
        for (int l = 0; l < 2; l++) {
            int f = tid + l * 256;
            int col = f >> 3;
            int kg  = f & 7;
            float4 v = *reinterpret_cast<const float4*>(&W[(long)(n0 + col) * K + k0 + kg * 4]);
            float4 t;
            t.x = tf32r(v.x); t.y = tf32r(v.y); t.z = tf32r(v.z); t.w = tf32r(v.w);
            *reinterpret_cast<float4*>(&Bs[col][kg * 4]) = t;
        }
        __syncthreads();

#pragma unroll
        for (int k8 = 0; k8 < 4; k8++) {
            const int kb = k8 * 8;
            uint32_t af[2][4];
#pragma unroll
            for (int mi = 0; mi < 2; mi++) {
                int rb = wr * 32 + mi * 16 + gID;
                af[mi][0] = __float_as_uint(As[rb    ][kb + tig]);
                af[mi][1] = __float_as_uint(As[rb + 8][kb + tig]);
                af[mi][2] = __float_as_uint(As[rb    ][kb + 4 + tig]);
                af[mi][3] = __float_as_uint(As[rb + 8][kb + 4 + tig]);
            }
            uint32_t bf[4][2];
#pragma unroll
            for (int ni = 0; ni < 4; ni++) {
                int cb = wc * 32 + ni * 8 + gID;
                bf[ni][0] = __float_as_uint(Bs[cb][kb + tig]);
                bf[ni][1] = __float_as_uint(Bs[cb][kb + 4 + tig]);
            }
#pragma unroll
            for (int mi = 0; mi < 2; mi++)
#pragma unroll
                for (int ni = 0; ni < 4; ni++)
                    mma_tf32(c[mi][ni], af[mi], bf[ni]);
        }
        __syncthreads();
    }

#pragma unroll
    for (int mi = 0; mi < 2; mi++) {
#pragma unroll
        for (int ni = 0; ni < 4; ni++) {
            int row = r0 + wr * 32 + mi * 16 + gID;
            int col = n0 + wc * 32 + ni * 8 + 2 * tig;
            float b0 = bias[col], b1 = bias[col + 1];
            float2 v0 = make_float2(c[mi][ni][0] + b0, c[mi][ni][1] + b1);
            float2 v1 = make_float2(c[mi][ni][2] + b0, c[mi][ni][3] + b1);
            *reinterpret_cast<float2*>(&C[(long)row * N + col]) = v0;
            *reinterpret_cast<float2*>(&C[(long)(row + 8) * N + col]) = v1;
        }
    }
}

// ================= persistent GRU scan: 8 warps, full-K per warp, no reduction =================
// grid = 128 blocks (m = bx>>5, j0 = (bx&31)*16), 256 threads = 8 warps.
// warp w = rowgroup (16 rows), covers full K=512 and all 48 gate-cols of this j-slice.
template<int LAYER>
__global__ __launch_bounds__(256, 1) void gru_scan(
    float* __restrict__ bufA, float* __restrict__ bufB,
    uint2* __restrict__ pakA, uint2* __restrict__ pakB,
    const float* __restrict__ gi,
    const uint4* __restrict__ whp,   // layer base already applied
    const float* __restrict__ bhh,
    const float* __restrict__ dm,
    float* __restrict__ outact,
    unsigned* __restrict__ syncctr)
{
    extern __shared__ unsigned Wpk[];   // 48 gate-cols x WSTRIDE words, fragment-permuted

    const int bx = blockIdx.x;
    const int m  = bx >> 5;
    const int j0 = (bx & 31) * 16;

    const int tid  = threadIdx.x;
    const int lane = tid & 31;
    const int w    = tid >> 5;    // rowgroup 0..7
    const int g    = lane >> 2;
    const int tg   = lane & 3;

    // ---- copy packed weights into smem (permuted for LDS.128 fragments) ----
    {
        const uint4* wb = whp + (long)m * Gg * 128;
        for (int f = tid; f < 48 * 128; f += 256) {
            int cc = f >> 7, qq = f & 127;
            int gr = (cc >> 4) * Hh + j0 + (cc & 15);
            uint4 v = wb[(long)gr * 128 + qq];
            int kp0 = qq * 2;
            *reinterpret_cast<uint2*>(Wpk + cc * WSTRIDE + 2 * permkp(kp0))     = make_uint2(v.x, v.y);
            *reinterpret_cast<uint2*>(Wpk + cc * WSTRIDE + 2 * permkp(kp0 + 1)) = make_uint2(v.z, v.w);
        }
    }
    __syncthreads();

    const long hb  = (long)m * Rr * Hh;
    const long hb2 = (long)m * Rr * 256;   // uint2 units
    const int  ar0 = w * 16 + g;
    const int  ar1 = w * 16 + 8 + g;

    // biases (constant across steps)
    float b_r[2][2], b_z[2][2], b_n[2][2];
#pragma unroll
    for (int u = 0; u < 2; u++)
#pragma unroll
        for (int jj = 0; jj < 2; jj++) {
            int j = j0 + u * 8 + 2 * tg + jj;
            b_r[u][jj] = __ldg(&bhh[m * Gg + j]);
            b_z[u][jj] = __ldg(&bhh[m * Gg + Hh + j]);
            b_n[u][jj] = __ldg(&bhh[m * Gg + 2 * Hh + j]);
        }

    // gi / dm prefetch registers for the upcoming step
    float2 gr2[2][2], gz2[2][2], gn2[2][2], dm2[2][2];
    auto prefetch_gi = [&](int t) {
#pragma unroll
        for (int rh = 0; rh < 2; rh++) {
            int row = w * 16 + rh * 8 + g;
            int p = row >> 5, b = row & 31;
            long girow = (LAYER == 0)
                ? ((long)(m * Ss + t) * Bb + b) * Gg
                : ((long)((m * Pp + p) * Ss + t) * Bb + b) * Gg;
            long obase = (((long)(m * Pp + p) * Ss + t) * Bb + b) * Hh;
#pragma unroll
            for (int u = 0; u < 2; u++) {
                int j = j0 + u * 8 + 2 * tg;
                gr2[rh][u] = __ldcg(reinterpret_cast<const float2*>(&gi[girow + j]));
                gz2[rh][u] = __ldcg(reinterpret_cast<const float2*>(&gi[girow + Hh + j]));
                gn2[rh][u] = __ldcg(reinterpret_cast<const float2*>(&gi[girow + 2 * Hh + j]));
                if (LAYER == 0)
                    dm2[rh][u] = __ldcg(reinterpret_cast<const float2*>(&dm[obase + j]));
            }
        }
    };
    prefetch_gi(0);

    for (int t = 0; t < Ss; t++) {
        const float* hc = (t & 1) ? bufB : bufA;
        float*       hn = (t & 1) ? bufA : bufB;
        const uint2* pc = (t & 1) ? pakB : pakA;
        uint2*       pn = (t & 1) ? pakA : pakB;

        // hold values (L2; consumed in epilogue)
        float2 ho2[2][2];
#pragma unroll
        for (int rh = 0; rh < 2; rh++) {
            int row = w * 16 + rh * 8 + g;
#pragma unroll
            for (int u = 0; u < 2; u++) {
                int j = j0 + u * 8 + 2 * tg;
                ho2[rh][u] = __ldcg(reinterpret_cast<const float2*>(&hc[hb + (long)row * Hh + j]));
            }
        }

        float cA[6][4], cB[6][4];
#pragma unroll
        for (int e = 0; e < 24; e++) { (&cA[0][0])[e] = 0.f; (&cB[0][0])[e] = 0.f; }

        auto fetchA = [&](int i, uint4* P) {
            P[0] = __ldcg(reinterpret_cast<const uint4*>(pc + hb2 + (long)ar0 * 256 + i * 8 + tg * 2));
            P[1] = __ldcg(reinterpret_cast<const uint4*>(pc + hb2 + (long)ar1 * 256 + i * 8 + tg * 2));
        };
        auto mmaI = [&](int i, const uint4* P) {
            uint32_t ahi[4] = {P[0].x, P[1].x, P[0].z, P[1].z};
            uint32_t alo[4] = {P[0].y, P[1].y, P[0].w, P[1].w};
#pragma unroll
            for (int tI = 0; tI < 6; tI++) {
                int cc = tI * 8 + g;
                uint4 Bv = *reinterpret_cast<const uint4*>(Wpk + cc * WSTRIDE + i * 16 + tg * 4);
                uint32_t bh[2] = {Bv.x, Bv.z};
                uint32_t bl[2] = {Bv.y, Bv.w};
                mma_bf16(cA[tI], ahi, bh);
                mma_bf16(cB[tI], ahi, bl);
                mma_bf16(cB[tI], alo, bh);
            }
        };

        uint4 P[4][2];
        fetchA(0, P[0]);
        fetchA(1, P[1]);
        fetchA(2, P[2]);
#pragma unroll 8
        for (int i = 0; i < 32; i++) {
            if (i < 29) fetchA(i + 3, P[(i + 3) & 3]);
            mmaI(i, P[i & 3]);
        }

        // ---- epilogue: gates + h update (all warps, both row halves) ----
#pragma unroll
        for (int rh = 0; rh < 2; rh++) {
            int row = w * 16 + rh * 8 + g;
            int p = row >> 5, b = row & 31;
            long obase = (((long)(m * Pp + p) * Ss + t) * Bb + b) * Hh;
            uint2 pk[2];
#pragma unroll
            for (int u = 0; u < 2; u++) {
                int j = j0 + u * 8 + 2 * tg;
                float hv[2];
#pragma unroll
                for (int jj = 0; jj < 2; jj++) {
                    int qi = rh * 2 + jj;
                    float ghr = cA[0 + u][qi] + cB[0 + u][qi] + b_r[u][jj];
                    float ghz = cA[2 + u][qi] + cB[2 + u][qi] + b_z[u][jj];
                    float ghn = cA[4 + u][qi] + cB[4 + u][qi] + b_n[u][jj];
                    float gih = (jj == 0) ? gr2[rh][u].x : gr2[rh][u].y;
                    float giz = (jj == 0) ? gz2[rh][u].x : gz2[rh][u].y;
                    float gin = (jj == 0) ? gn2[rh][u].x : gn2[rh][u].y;
                    float hold = (jj == 0) ? ho2[rh][u].x : ho2[rh][u].y;
                    float rg = sigmoidf_(gih + ghr);
                    float zg = sigmoidf_(giz + ghz);
                    float ng = tanhf(gin + rg * ghn);
                    hv[jj] = (1.0f - zg) * ng + zg * hold;
                }
                __stcg(reinterpret_cast<float2*>(&hn[hb + (long)row * Hh + j]),
                       make_float2(hv[0], hv[1]));
                pk[u] = pack_hilo(hv[0], hv[1]);
                float2 oa;
                if (LAYER == 0) {
                    oa = make_float2(hv[0] * dm2[rh][u].x, hv[1] * dm2[rh][u].y);
                } else {
                    oa = make_float2(fmaxf(hv[0], 0.f) + 0.01f * fminf(hv[0], 0.f),
                                     fmaxf(hv[1], 0.f) + 0.01f * fminf(hv[1], 0.f));
                }
                __stcg(reinterpret_cast<float2*>(&outact[obase + j]), oa);
            }
            // one 128-bit permuted packed store (covers u=0 and u=1)
            __stcg(reinterpret_cast<uint4*>(pn + hb2 + (long)row * 256 + (j0 >> 1) + tg * 2),
                   make_uint4(pk[0].x, pk[0].y, pk[1].x, pk[1].y));
        }

        // ---- prefetch next step's gi/dm (hidden behind barrier wait) ----
        if (t + 1 < Ss) prefetch_gi(t + 1);

        // ---- per-model grid barrier ----
        __syncthreads();
        if (tid == 0) {
            __threadfence();
            atomicAdd(&syncctr[m], 1u);
            unsigned target = 32u * (unsigned)(t + 1);
            volatile unsigned* vc = (volatile unsigned*)&syncctr[m];
            while (*vc < target) __nanosleep(32);
        }
        __syncthreads();
    }
}

// ---------------- mean / var ----------------
__global__ void meanvar_kernel(const float* __restrict__ preds,
                               float* __restrict__ out_mean, float* __restrict__ out_var)
{
    const int n = Ss * Bb * Oo;
    int idx = blockIdx.x * blockDim.x + threadIdx.x;
    if (idx >= n) return;
    float v[16];
    float s = 0.f;
#pragma unroll
    for (int mp = 0; mp < 16; mp++) {
        v[mp] = preds[(long)mp * n + idx];
        s += v[mp];
    }
    float mu = s * (1.0f / 16.0f);
    float qq = 0.f;
#pragma unroll
    for (int mp = 0; mp < 16; mp++) {
        float d = v[mp] - mu;
        qq += d * d;
    }
    out_mean[idx] = mu;
    out_var[idx]  = qq * (1.0f / 15.0f);
}

// ---------------- host launch ----------------
extern "C" void kernel_launch(void* const* d_in, const int* in_sizes, int n_in,
                              void* d_out, int out_size)
{
    const float* input  = (const float*)d_in[0];
    const float* hidden = (const float*)d_in[1];
    const float* w_ih0  = (const float*)d_in[2];
    const float* w_hh0  = (const float*)d_in[3];
    const float* b_ih0  = (const float*)d_in[4];
    const float* b_hh0  = (const float*)d_in[5];
    const float* w_ih1  = (const float*)d_in[6];
    const float* w_hh1  = (const float*)d_in[7];
    const float* b_ih1  = (const float*)d_in[8];
    const float* b_hh1  = (const float*)d_in[9];
    const float* lin_w  = (const float*)d_in[10];
    const float* lin_b  = (const float*)d_in[11];
    const float* dm     = (const float*)d_in[12];

    float* out = (float*)d_out;
    float* out_mean   = out;
    float* out_var    = out + (size_t)Ss * Bb * Oo;
    float* preds      = out + 2 * (size_t)Ss * Bb * Oo;
    float* hidden_out = preds + (size_t)Mm * Pp * Ss * Bb * Oo;

    float *gi0, *y0m, *gi1, *a1, *h0a, *h0b, *h1a, *h1b;
    uint4 *p0a, *p0b, *p1a, *p1b, *whp;
    unsigned* syncp;
    cudaGetSymbolAddress((void**)&gi0, g_gi0);
    cudaGetSymbolAddress((void**)&y0m, g_y0m);
    cudaGetSymbolAddress((void**)&gi1, g_gi1);
    cudaGetSymbolAddress((void**)&a1,  g_a1);
    cudaGetSymbolAddress((void**)&h0a, g_h0a);
    cudaGetSymbolAddress((void**)&h0b, g_h0b);
    cudaGetSymbolAddress((void**)&h1a, g_h1a);
    cudaGetSymbolAddress((void**)&h1b, g_h1b);
    cudaGetSymbolAddress((void**)&p0a, g_hp0a);
    cudaGetSymbolAddress((void**)&p0b, g_hp0b);
    cudaGetSymbolAddress((void**)&p1a, g_hp1a);
    cudaGetSymbolAddress((void**)&p1b, g_hp1b);
    cudaGetSymbolAddress((void**)&whp, g_whhp);
    cudaGetSymbolAddress((void**)&syncp, g_sync);

    cudaFuncSetAttribute(gru_scan<0>, cudaFuncAttributeMaxDynamicSharedMemorySize, SCAN_SMEM_BYTES);
    cudaFuncSetAttribute(gru_scan<1>, cudaFuncAttributeMaxDynamicSharedMemorySize, SCAN_SMEM_BYTES);

    // 0) split+pack recurrent weights (bf16 hi/lo)
    {
        int n2 = 2 * Mm * Gg * (Hh / 2);
        split_pack_kernel<<<(n2 + 255) / 256, 256>>>(w_hh0, w_hh1, (uint2*)whp);
    }

    // 1) init hidden (fp32 + permuted packed) + zero barrier counters
    {
        int n2 = Mm * Pp * Bb * 256;
        init_hidden_kernel<<<(n2 + 255) / 256, 256>>>(hidden, h0a, h1a,
                                                      (uint2*)p0a, (uint2*)p1a, syncp);
    }

    // 2) gi0 = input @ w_ih0^T + b_ih0  (TF32)
    {
        dim3 grid(Gg / 64, (Ss * Bb) / 128, Mm);
        gemm_tf32_bias<<<grid, 256>>>(input, 0L,
                                      w_ih0, (long)Gg * Ii,
                                      b_ih0, Gg,
                                      gi0, (long)Ss * Bb * Gg,
                                      Ss * Bb, Gg, Ii);
    }

    // 3) layer-0 persistent scan
    gru_scan<0><<<128, 256, SCAN_SMEM_BYTES>>>(h0a, h0b, (uint2*)p0a, (uint2*)p0b, gi0,
                                               whp, b_hh0, dm, y0m, syncp);

    // 4) gi1 = y0m @ w_ih1^T + b_ih1 (TF32)
    {
        dim3 grid(Gg / 64, (Pp * Ss * Bb) / 128, Mm);
        gemm_tf32_bias<<<grid, 256>>>(y0m, (long)Pp * Ss * Bb * Hh,
                                      w_ih1, (long)Gg * Hh,
                                      b_ih1, Gg,
                                      gi1, (long)Pp * Ss * Bb * Gg,
                                      Pp * Ss * Bb, Gg, Hh);
    }

    // 5) layer-1 persistent scan
    gru_scan<1><<<128, 256, SCAN_SMEM_BYTES>>>(h1a, h1b, (uint2*)p1a, (uint2*)p1b, gi1,
                                               whp + (long)Mm * Gg * 128, b_hh1,
                                               nullptr, a1, syncp + 4);

    // 6) preds = a1 @ lin_w^T + lin_b (TF32)
    {
        dim3 grid(Oo / 64, (Pp * Ss * Bb) / 128, Mm);
        gemm_tf32_bias<<<grid, 256>>>(a1, (long)Pp * Ss * Bb * Hh,
                                      lin_w, (long)Oo * Hh,
                                      lin_b, Oo,
                                      preds, (long)Pp * Ss * Bb * Oo,
                                      Pp * Ss * Bb, Oo, Hh);
    }

    // 7) mean / var
    meanvar_kernel<<<(Ss * Bb * Oo + 255) / 256, 256>>>(preds, out_mean, out_var);

    // 8) hidden out (256 steps even -> final h in 'a' buffers)
    hidden_out_kernel<<<(Mm*Pp*Bb*Hh + 255) / 256, 256>>>(h0a, h1a, hidden_out);
}